// round 7
// baseline (speedup 1.0000x reference)
#include <cuda_runtime.h>
#include <cuda_bf16.h>
#include <stdint.h>
#include <math.h>

#define B_ 4
#define T_ 2048
#define C_ 1024
#define H_ 16
#define D_ 64
#define M_ (B_*T_)   // 8192

// ---------------------------------------------------------------------------
// Scratch (allocation-free __device__ globals)
// ---------------------------------------------------------------------------
__device__ unsigned short g_qkvh[25165824];    // qkv hi bf16 [8192][3072]
__device__ unsigned short g_qkvl[25165824];    // qkv lo
__device__ unsigned short g_xh[8388608];       // x hi bf16 [8192][1024]
__device__ unsigned short g_xl[8388608];
__device__ unsigned short g_wqkvh[3145728];    // w_qkv^T hi [3072][1024]
__device__ unsigned short g_wqkvl[3145728];
__device__ unsigned short g_wprojh[1048576];   // w_proj^T hi [1024][1024]
__device__ unsigned short g_wprojl[1048576];
__device__ unsigned short g_atth[8388608];     // attention out hi [8192][1024]
__device__ unsigned short g_attl[8388608];

// ---------------------------------------------------------------------------
// Helpers (sm_103 baseline: ldmatrix, mma.sync, cp.async)
// ---------------------------------------------------------------------------
__device__ __forceinline__ uint32_t smem_u32(const void* p) {
    uint32_t a;
    asm("{ .reg .u64 t; cvta.to.shared.u64 t, %1; cvt.u32.u64 %0, t; }"
        : "=r"(a) : "l"(p));
    return a;
}

__device__ __forceinline__ void ldsm_x4(uint32_t& r0, uint32_t& r1,
                                        uint32_t& r2, uint32_t& r3, uint32_t a) {
    asm volatile("ldmatrix.sync.aligned.m8n8.x4.shared.b16 {%0,%1,%2,%3}, [%4];"
                 : "=r"(r0), "=r"(r1), "=r"(r2), "=r"(r3) : "r"(a));
}

__device__ __forceinline__ void ldsm_x2(uint32_t& r0, uint32_t& r1, uint32_t a) {
    asm volatile("ldmatrix.sync.aligned.m8n8.x2.shared.b16 {%0,%1}, [%2];"
                 : "=r"(r0), "=r"(r1) : "r"(a));
}

__device__ __forceinline__ void ldsm_x4t(uint32_t* r, uint32_t a) {
    asm volatile("ldmatrix.sync.aligned.m8n8.x4.trans.shared.b16 {%0,%1,%2,%3}, [%4];"
                 : "=r"(r[0]), "=r"(r[1]), "=r"(r[2]), "=r"(r[3]) : "r"(a));
}

__device__ __forceinline__ void mma16816(float* c, const uint32_t* A, const uint32_t* Bv) {
    asm volatile(
        "mma.sync.aligned.m16n8k16.row.col.f32.bf16.bf16.f32 "
        "{%0,%1,%2,%3}, {%4,%5,%6,%7}, {%8,%9}, {%0,%1,%2,%3};"
        : "+f"(c[0]), "+f"(c[1]), "+f"(c[2]), "+f"(c[3])
        : "r"(A[0]), "r"(A[1]), "r"(A[2]), "r"(A[3]), "r"(Bv[0]), "r"(Bv[1]));
}

__device__ __forceinline__ void cp16(uint32_t dst, const void* src) {
    asm volatile("cp.async.cg.shared.global [%0], [%1], 16;" :: "r"(dst), "l"(src));
}
#define CP_COMMIT() asm volatile("cp.async.commit_group;" ::: "memory")
#define CP_WAIT0()  asm volatile("cp.async.wait_group 0;" ::: "memory")
#define CP_WAIT1()  asm volatile("cp.async.wait_group 1;" ::: "memory")

// pack two fp32 -> bf16x2 {lo=p0, hi=p1}
__device__ __forceinline__ uint32_t pack_bf16(float p0, float p1) {
    uint32_t r;
    asm("cvt.rn.bf16x2.f32 %0, %1, %2;" : "=r"(r) : "f"(p1), "f"(p0));
    return r;
}

// split pair into hi bf16x2 + residual bf16x2
__device__ __forceinline__ void mk2(float p0, float p1, uint32_t& hi, uint32_t& lo) {
    uint32_t h = pack_bf16(p0, p1);
    float r0 = p0 - __uint_as_float(h << 16);
    float r1 = p1 - __uint_as_float(h & 0xffff0000u);
    hi = h;
    lo = pack_bf16(r0, r1);
}

__device__ __forceinline__ void split2(float x, unsigned short& hh, unsigned short& ll) {
    __nv_bfloat16 hb = __float2bfloat16(x);
    hh = reinterpret_cast<unsigned short&>(hb);
    float r = x - __bfloat162float(hb);
    __nv_bfloat16 lb = __float2bfloat16(r);
    ll = reinterpret_cast<unsigned short&>(lb);
}

// ---------------------------------------------------------------------------
// Prep kernels
// ---------------------------------------------------------------------------
__global__ void __launch_bounds__(256) pack_split_kernel(
    const float* __restrict__ src, unsigned short* __restrict__ hi,
    unsigned short* __restrict__ lo)
{
    int i = blockIdx.x * 256 + threadIdx.x;
    float4 v = ((const float4*)src)[i];
    unsigned short h[4], l[4];
    split2(v.x, h[0], l[0]); split2(v.y, h[1], l[1]);
    split2(v.z, h[2], l[2]); split2(v.w, h[3], l[3]);
    ((uint2*)hi)[i] = make_uint2((uint32_t)h[0] | ((uint32_t)h[1] << 16),
                                 (uint32_t)h[2] | ((uint32_t)h[3] << 16));
    ((uint2*)lo)[i] = make_uint2((uint32_t)l[0] | ((uint32_t)l[1] << 16),
                                 (uint32_t)l[2] | ((uint32_t)l[3] << 16));
}

__global__ void __launch_bounds__(256) transpose_pack_kernel(
    const float* __restrict__ w, unsigned short* __restrict__ th,
    unsigned short* __restrict__ tl, int K, int N)
{
    __shared__ float tile[32][33];
    const int k0 = blockIdx.y * 32, n0 = blockIdx.x * 32;
    const int tx = threadIdx.x, ty = threadIdx.y;   // 32 x 8
    #pragma unroll
    for (int i = 0; i < 32; i += 8)
        tile[ty + i][tx] = w[(size_t)(k0 + ty + i) * N + n0 + tx];
    __syncthreads();
    #pragma unroll
    for (int i = 0; i < 32; i += 8) {
        int n = n0 + ty + i;
        int k = k0 + tx;
        float v = tile[tx][ty + i];
        unsigned short hh, ll;
        split2(v, hh, ll);
        th[(size_t)n * K + k] = hh;
        tl[(size_t)n * K + k] = ll;
    }
}

// ---------------------------------------------------------------------------
// Split-bf16 mma.sync GEMM: out = A @ B^T + bias.
// BM=BN=128, BK=32, 8 warps (2x4), warp tile 64x32.
// 3-stage cp.async pipeline (32KB/stage); each fragment ldmatrix'd once.
// ---------------------------------------------------------------------------
#define GEMM_SMEM (3*32768)

__global__ void __launch_bounds__(256, 2) gemm_mma_kernel(
    const unsigned short* __restrict__ ah, const unsigned short* __restrict__ al,
    const unsigned short* __restrict__ bh, const unsigned short* __restrict__ bl,
    const float* __restrict__ bias, float* __restrict__ outf,
    unsigned short* __restrict__ outh, unsigned short* __restrict__ outl,
    int M, int N, int K)
{
    extern __shared__ char smc[];
    const uint32_t sbase = smem_u32(smc);
    const int tid  = threadIdx.x;
    const int wid  = tid >> 5, lane = tid & 31;
    const int wm   = wid >> 2, wn = wid & 3;
    const int mBase = blockIdx.y * 128;
    const int nBase = blockIdx.x * 128;
    const int nk = K >> 5;

    const int r0c = tid >> 2;
    const int c0c = tid & 3;
    auto sw = [](int r, int c) { return r * 64 + ((c ^ ((r >> 1) & 3)) << 4); };

    auto issue = [&](int ks, int stage) {
        const int kb = ks << 5;
        const unsigned short* gs[4] = { ah, al, bh, bl };
        #pragma unroll
        for (int part = 0; part < 4; part++) {
            const unsigned short* g = gs[part] +
                (size_t)((part < 2) ? mBase : nBase) * K + kb;
            uint32_t pb = sbase + stage * 32768 + part * 8192;
            cp16(pb + sw(r0c,      c0c), g + (size_t)r0c        * K + c0c * 8);
            cp16(pb + sw(r0c + 64, c0c), g + (size_t)(r0c + 64) * K + c0c * 8);
        }
        CP_COMMIT();
    };

    float acc[4][4][4];
    #pragma unroll
    for (int i = 0; i < 4; i++)
        #pragma unroll
        for (int j = 0; j < 4; j++)
            #pragma unroll
            for (int r = 0; r < 4; r++) acc[i][j][r] = 0.f;

    const int la_row = lane & 15;
    const int la_kh  = lane >> 4;
    const int lb_row = lane & 7;
    const int lb_kh  = (lane >> 3) & 1;

    issue(0, 0);
    issue(1, 1);

    for (int ks = 0; ks < nk; ks++) {
        if (ks + 1 >= nk) { CP_WAIT0(); } else { CP_WAIT1(); }
        __syncthreads();
        if (ks + 2 < nk) issue(ks + 2, (ks + 2) % 3);

        const uint32_t sAh = sbase + (ks % 3) * 32768;
        const uint32_t sAl = sAh + 8192;
        const uint32_t sBh = sAh + 16384;
        const uint32_t sBl = sAh + 24576;

        #pragma unroll
        for (int kk = 0; kk < 2; kk++) {
            const int ch_a = kk * 2 + la_kh;
            const int ch_b = kk * 2 + lb_kh;

            uint32_t Ahf[4][4], Bhf[4][2];
            #pragma unroll
            for (int i = 0; i < 4; i++) {
                int row = wm * 64 + i * 16 + la_row;
                ldsm_x4(Ahf[i][0], Ahf[i][1], Ahf[i][2], Ahf[i][3], sAh + sw(row, ch_a));
            }
            #pragma unroll
            for (int j = 0; j < 4; j++) {
                int row = wn * 32 + j * 8 + lb_row;
                ldsm_x2(Bhf[j][0], Bhf[j][1], sBh + sw(row, ch_b));
            }
            #pragma unroll
            for (int i = 0; i < 4; i++)
                #pragma unroll
                for (int j = 0; j < 4; j++) mma16816(acc[i][j], Ahf[i], Bhf[j]);

            // Al x Bh (reuse Bh fragments)
            {
                uint32_t Alf[4][4];
                #pragma unroll
                for (int i = 0; i < 4; i++) {
                    int row = wm * 64 + i * 16 + la_row;
                    ldsm_x4(Alf[i][0], Alf[i][1], Alf[i][2], Alf[i][3], sAl + sw(row, ch_a));
                }
                #pragma unroll
                for (int i = 0; i < 4; i++)
                    #pragma unroll
                    for (int j = 0; j < 4; j++) mma16816(acc[i][j], Alf[i], Bhf[j]);
            }

            // Ah x Bl (reuse Ah fragments)
            {
                uint32_t Blf[4][2];
                #pragma unroll
                for (int j = 0; j < 4; j++) {
                    int row = wn * 32 + j * 8 + lb_row;
                    ldsm_x2(Blf[j][0], Blf[j][1], sBl + sw(row, ch_b));
                }
                #pragma unroll
                for (int i = 0; i < 4; i++)
                    #pragma unroll
                    for (int j = 0; j < 4; j++) mma16816(acc[i][j], Ahf[i], Blf[j]);
            }
        }
    }

    // Epilogue
    const int g = lane >> 2, q = lane & 3;
    #pragma unroll
    for (int i = 0; i < 4; i++) {
        const int row0 = mBase + wm * 64 + i * 16 + g;
        #pragma unroll
        for (int j = 0; j < 4; j++) {
            const int col = nBase + wn * 32 + j * 8 + q * 2;
            float2 bb = *(const float2*)(bias + col);
            float v0x = acc[i][j][0] + bb.x, v0y = acc[i][j][1] + bb.y;
            float v1x = acc[i][j][2] + bb.x, v1y = acc[i][j][3] + bb.y;
            if (outh) {
                uint32_t h0, l0, h1, l1;
                mk2(v0x, v0y, h0, l0);
                mk2(v1x, v1y, h1, l1);
                *(uint32_t*)(outh + (size_t)row0 * N + col)       = h0;
                *(uint32_t*)(outl + (size_t)row0 * N + col)       = l0;
                *(uint32_t*)(outh + (size_t)(row0 + 8) * N + col) = h1;
                *(uint32_t*)(outl + (size_t)(row0 + 8) * N + col) = l1;
            } else {
                *(float2*)(outf + (size_t)row0 * N + col)       = make_float2(v0x, v0y);
                *(float2*)(outf + (size_t)(row0 + 8) * N + col) = make_float2(v1x, v1y);
            }
        }
    }
}

// ---------------------------------------------------------------------------
// Tensor-core flash attention (causal, split-bf16).
// Block = 128 q rows of one (b,h), 8 warps (m16 each), 256 threads.
// K/V in 3-stage cp.async pipeline (32KB/stage); Q resident (32KB).
// ---------------------------------------------------------------------------
#define ATTN_SMEM (32768 + 3*32768)

__global__ void __launch_bounds__(256, 1) attn_mma_kernel(
    const unsigned short* __restrict__ qkvh,
    const unsigned short* __restrict__ qkvl,
    unsigned short* __restrict__ atth,
    unsigned short* __restrict__ attl)
{
    extern __shared__ char smc[];
    const uint32_t sb = smem_u32(smc);
    const int tid = threadIdx.x, lane = tid & 31, w = tid >> 5;
    const int bh = blockIdx.y, b = bh >> 4, hd = bh & 15;
    const int qb = (int)gridDim.x - 1 - (int)blockIdx.x;   // big blocks first
    const int q0 = qb * 128;
    const int nkt = 2 * qb + 2;

    const size_t base = (size_t)b * T_ * 3072 + hd * 64;
    const unsigned short* qh = qkvh + base;
    const unsigned short* qlp = qkvl + base;
    const unsigned short* kh = qh + 1024;
    const unsigned short* kl = qlp + 1024;
    const unsigned short* vh = qh + 2048;
    const unsigned short* vl = qlp + 2048;

    const uint32_t sQh = sb, sQl = sb + 16384;
    auto stage0 = [&](int s) { return sb + 32768 + s * 32768; };
    auto off = [](int r, int c) { return r * 128 + ((c ^ (r & 7)) << 4); };

    auto issue_kv = [&](int kt, int s) {
        uint32_t sn = stage0(s);
        const size_t kb = (size_t)kt * 64;
        #pragma unroll
        for (int i = 0; i < 2; i++) {
            int idx = i * 256 + tid;
            int r = idx >> 3, c = idx & 7;
            const size_t g = (kb + r) * 3072 + c * 8;
            cp16(sn +         off(r, c), kh + g);
            cp16(sn + 8192 +  off(r, c), kl + g);
            cp16(sn + 16384 + off(r, c), vh + g);
            cp16(sn + 24576 + off(r, c), vl + g);
        }
        CP_COMMIT();
    };

    // prologue: group0 = Q + K/V tile 0; group1 = K/V tile 1
    #pragma unroll
    for (int i = 0; i < 4; i++) {
        int idx = i * 256 + tid;
        int r = idx >> 3, c = idx & 7;
        const size_t g = (size_t)(q0 + r) * 3072 + c * 8;
        cp16(sQh + off(r, c), qh + g);
        cp16(sQl + off(r, c), qlp + g);
    }
    issue_kv(0, 0);      // commits Q + tile0 together
    issue_kv(1, 1);

    float O[8][4], s[8][4];
    #pragma unroll
    for (int j = 0; j < 8; j++) { O[j][0] = O[j][1] = O[j][2] = O[j][3] = 0.f; }
    float m_lo = -1e30f, m_hi = -1e30f, l_lo = 0.f, l_hi = 0.f;

    const int la_row = lane & 15, la_kh = lane >> 4;
    const int kb_row = ((lane >> 4) << 3) + (lane & 7);
    const int kb_ch  = (lane >> 3) & 1;
    const int vb_row = (((lane >> 3) & 1) << 3) + (lane & 7);
    const int vb_ch  = lane >> 4;
    const int rowq_lo = q0 + w * 16 + (lane >> 2);

    for (int kt = 0; kt < nkt; kt++) {
        if (kt + 1 >= nkt) { CP_WAIT0(); } else { CP_WAIT1(); }
        __syncthreads();
        if (kt + 2 < nkt) issue_kv(kt + 2, (kt + 2) % 3);

        const int k0 = kt * 64;
        const bool active = (k0 <= q0 + w * 16 + 15);
        if (active) {
            const uint32_t cK  = stage0(kt % 3);
            const uint32_t cKl = cK + 8192;
            const uint32_t cV  = cK + 16384;
            const uint32_t cVl = cK + 24576;

            // ---- S = Q K^T (split: QhKh + QlKh + QhKl) ----
            #pragma unroll
            for (int j = 0; j < 8; j++) { s[j][0] = s[j][1] = s[j][2] = s[j][3] = 0.f; }
            #pragma unroll
            for (int kk = 0; kk < 4; kk++) {
                uint32_t aqh[4], aql[4];
                ldsm_x4(aqh[0], aqh[1], aqh[2], aqh[3],
                        sQh + off(w * 16 + la_row, 2 * kk + la_kh));
                ldsm_x4(aql[0], aql[1], aql[2], aql[3],
                        sQl + off(w * 16 + la_row, 2 * kk + la_kh));
                #pragma unroll
                for (int j2 = 0; j2 < 4; j2++) {
                    uint32_t bk[4];
                    ldsm_x4(bk[0], bk[1], bk[2], bk[3],
                            cK + off(16 * j2 + kb_row, 2 * kk + kb_ch));
                    mma16816(s[2 * j2],     aqh, bk);
                    mma16816(s[2 * j2 + 1], aqh, bk + 2);
                    mma16816(s[2 * j2],     aql, bk);
                    mma16816(s[2 * j2 + 1], aql, bk + 2);
                    ldsm_x4(bk[0], bk[1], bk[2], bk[3],
                            cKl + off(16 * j2 + kb_row, 2 * kk + kb_ch));
                    mma16816(s[2 * j2],     aqh, bk);
                    mma16816(s[2 * j2 + 1], aqh, bk + 2);
                }
            }

            // ---- online softmax ----
            const bool masked = (k0 + 63 > q0 + w * 16);
            float rm_lo = -1e30f, rm_hi = -1e30f;
            #pragma unroll
            for (int j = 0; j < 8; j++) {
                int colb = k0 + 8 * j + 2 * (lane & 3);
                #pragma unroll
                for (int e = 0; e < 2; e++) {
                    float v = s[j][e] * 0.125f;
                    if (masked && (colb + e) > rowq_lo) v = -1e30f;
                    s[j][e] = v; rm_lo = fmaxf(rm_lo, v);
                    float v2 = s[j][2 + e] * 0.125f;
                    if (masked && (colb + e) > rowq_lo + 8) v2 = -1e30f;
                    s[j][2 + e] = v2; rm_hi = fmaxf(rm_hi, v2);
                }
            }
            rm_lo = fmaxf(rm_lo, __shfl_xor_sync(0xffffffffu, rm_lo, 1));
            rm_lo = fmaxf(rm_lo, __shfl_xor_sync(0xffffffffu, rm_lo, 2));
            rm_hi = fmaxf(rm_hi, __shfl_xor_sync(0xffffffffu, rm_hi, 1));
            rm_hi = fmaxf(rm_hi, __shfl_xor_sync(0xffffffffu, rm_hi, 2));
            float mn_lo = fmaxf(m_lo, rm_lo), mn_hi = fmaxf(m_hi, rm_hi);
            float corr_lo = __expf(m_lo - mn_lo), corr_hi = __expf(m_hi - mn_hi);
            m_lo = mn_lo; m_hi = mn_hi;
            float ps_lo = 0.f, ps_hi = 0.f;
            #pragma unroll
            for (int j = 0; j < 8; j++) {
                s[j][0] = __expf(s[j][0] - mn_lo);
                s[j][1] = __expf(s[j][1] - mn_lo);
                s[j][2] = __expf(s[j][2] - mn_hi);
                s[j][3] = __expf(s[j][3] - mn_hi);
                ps_lo += s[j][0] + s[j][1];
                ps_hi += s[j][2] + s[j][3];
            }
            ps_lo += __shfl_xor_sync(0xffffffffu, ps_lo, 1);
            ps_lo += __shfl_xor_sync(0xffffffffu, ps_lo, 2);
            ps_hi += __shfl_xor_sync(0xffffffffu, ps_hi, 1);
            ps_hi += __shfl_xor_sync(0xffffffffu, ps_hi, 2);
            l_lo = l_lo * corr_lo + ps_lo;
            l_hi = l_hi * corr_hi + ps_hi;
            #pragma unroll
            for (int j = 0; j < 8; j++) {
                O[j][0] *= corr_lo; O[j][1] *= corr_lo;
                O[j][2] *= corr_hi; O[j][3] *= corr_hi;
            }

            // ---- O += P V (split: PhVh + PlVh + PhVl) ----
            #pragma unroll
            for (int t = 0; t < 4; t++) {
                uint32_t ph[4], pl[4];
                mk2(s[2 * t][0],     s[2 * t][1],     ph[0], pl[0]);
                mk2(s[2 * t][2],     s[2 * t][3],     ph[1], pl[1]);
                mk2(s[2 * t + 1][0], s[2 * t + 1][1], ph[2], pl[2]);
                mk2(s[2 * t + 1][2], s[2 * t + 1][3], ph[3], pl[3]);
                #pragma unroll
                for (int j2 = 0; j2 < 4; j2++) {
                    uint32_t bv[4];
                    ldsm_x4t(bv, cV + off(16 * t + vb_row, 2 * j2 + vb_ch));
                    mma16816(O[2 * j2],     ph, bv);
                    mma16816(O[2 * j2 + 1], ph, bv + 2);
                    mma16816(O[2 * j2],     pl, bv);
                    mma16816(O[2 * j2 + 1], pl, bv + 2);
                    ldsm_x4t(bv, cVl + off(16 * t + vb_row, 2 * j2 + vb_ch));
                    mma16816(O[2 * j2],     ph, bv);
                    mma16816(O[2 * j2 + 1], ph, bv + 2);
                }
            }
        }
    }

    // ---- epilogue: normalize, split-bf16, write ----
    const float inv_lo = 1.f / l_lo, inv_hi = 1.f / l_hi;
    const size_t row_lo = (size_t)(b * T_) + q0 + w * 16 + (lane >> 2);
    const int colb = hd * 64 + 2 * (lane & 3);
    #pragma unroll
    for (int j = 0; j < 8; j++) {
        const int col = colb + 8 * j;
        uint32_t h0, l0, h1, l1;
        mk2(O[j][0] * inv_lo, O[j][1] * inv_lo, h0, l0);
        mk2(O[j][2] * inv_hi, O[j][3] * inv_hi, h1, l1);
        *(uint32_t*)(atth + row_lo * C_ + col)       = h0;
        *(uint32_t*)(attl + row_lo * C_ + col)       = l0;
        *(uint32_t*)(atth + (row_lo + 8) * C_ + col) = h1;
        *(uint32_t*)(attl + (row_lo + 8) * C_ + col) = l1;
    }
}

// ---------------------------------------------------------------------------
extern "C" void kernel_launch(void* const* d_in, const int* in_sizes, int n_in,
                              void* d_out, int out_size)
{
    const float* x      = (const float*)d_in[0];
    const float* w_qkv  = (const float*)d_in[1];
    const float* b_qkv  = (const float*)d_in[2];
    const float* w_proj = (const float*)d_in[3];
    const float* b_proj = (const float*)d_in[4];
    float* out = (float*)d_out;

    unsigned short *qvh, *qvl, *xh, *xl, *wqh, *wql, *wph, *wpl, *ath, *atl;
    cudaGetSymbolAddress((void**)&qvh, g_qkvh);
    cudaGetSymbolAddress((void**)&qvl, g_qkvl);
    cudaGetSymbolAddress((void**)&xh, g_xh);
    cudaGetSymbolAddress((void**)&xl, g_xl);
    cudaGetSymbolAddress((void**)&wqh, g_wqkvh);
    cudaGetSymbolAddress((void**)&wql, g_wqkvl);
    cudaGetSymbolAddress((void**)&wph, g_wprojh);
    cudaGetSymbolAddress((void**)&wpl, g_wprojl);
    cudaGetSymbolAddress((void**)&ath, g_atth);
    cudaGetSymbolAddress((void**)&atl, g_attl);

    cudaFuncSetAttribute(gemm_mma_kernel,
                         cudaFuncAttributeMaxDynamicSharedMemorySize, GEMM_SMEM);
    cudaFuncSetAttribute(attn_mma_kernel,
                         cudaFuncAttributeMaxDynamicSharedMemorySize, ATTN_SMEM);

    // 0) pack inputs to split bf16
    pack_split_kernel<<<M_*C_/1024, 256>>>(x, xh, xl);
    transpose_pack_kernel<<<dim3(3*C_/32, C_/32), dim3(32, 8)>>>(w_qkv, wqh, wql, C_, 3*C_);
    transpose_pack_kernel<<<dim3(C_/32, C_/32), dim3(32, 8)>>>(w_proj, wph, wpl, C_, C_);

    // 1) qkv = x @ w_qkv + b_qkv  -> split-bf16 qkv
    gemm_mma_kernel<<<dim3(3*C_/128, M_/128), 256, GEMM_SMEM>>>(
        xh, xl, wqh, wql, b_qkv, nullptr, qvh, qvl, M_, 3*C_, C_);

    // 2) tensor-core causal flash attention -> split-bf16 att
    attn_mma_kernel<<<dim3(T_/128, B_*H_), 256, ATTN_SMEM>>>(qvh, qvl, ath, atl);

    // 3) out = att @ w_proj + b_proj  -> fp32
    gemm_mma_kernel<<<dim3(C_/128, M_/128), 256, GEMM_SMEM>>>(
        ath, atl, wph, wpl, b_proj, out, nullptr, nullptr, M_, C_, C_);
}

// round 8
// speedup vs baseline: 1.0208x; 1.0208x over previous
#include <cuda_runtime.h>
#include <cuda_bf16.h>
#include <stdint.h>
#include <math.h>

#define B_ 4
#define T_ 2048
#define C_ 1024
#define H_ 16
#define D_ 64
#define M_ (B_*T_)   // 8192

// ---------------------------------------------------------------------------
// Scratch (allocation-free __device__ globals)
// ---------------------------------------------------------------------------
__device__ unsigned short g_qkvh[25165824];    // qkv hi bf16 [8192][3072]
__device__ unsigned short g_qkvl[25165824];    // qkv lo
__device__ unsigned short g_xh[8388608];       // x hi bf16 [8192][1024]
__device__ unsigned short g_xl[8388608];
__device__ unsigned short g_wqkvh[3145728];    // w_qkv^T hi [3072][1024]
__device__ unsigned short g_wqkvl[3145728];
__device__ unsigned short g_wprojh[1048576];   // w_proj^T hi [1024][1024]
__device__ unsigned short g_wprojl[1048576];
__device__ unsigned short g_atth[8388608];     // attention out hi [8192][1024]
__device__ unsigned short g_attl[8388608];

// ---------------------------------------------------------------------------
// Helpers (sm_103 baseline: ldmatrix, mma.sync, cp.async)
// ---------------------------------------------------------------------------
__device__ __forceinline__ uint32_t smem_u32(const void* p) {
    uint32_t a;
    asm("{ .reg .u64 t; cvta.to.shared.u64 t, %1; cvt.u32.u64 %0, t; }"
        : "=r"(a) : "l"(p));
    return a;
}

__device__ __forceinline__ void ldsm_x4(uint32_t& r0, uint32_t& r1,
                                        uint32_t& r2, uint32_t& r3, uint32_t a) {
    asm volatile("ldmatrix.sync.aligned.m8n8.x4.shared.b16 {%0,%1,%2,%3}, [%4];"
                 : "=r"(r0), "=r"(r1), "=r"(r2), "=r"(r3) : "r"(a));
}

__device__ __forceinline__ void ldsm_x2(uint32_t& r0, uint32_t& r1, uint32_t a) {
    asm volatile("ldmatrix.sync.aligned.m8n8.x2.shared.b16 {%0,%1}, [%2];"
                 : "=r"(r0), "=r"(r1) : "r"(a));
}

__device__ __forceinline__ void ldsm_x4t(uint32_t* r, uint32_t a) {
    asm volatile("ldmatrix.sync.aligned.m8n8.x4.trans.shared.b16 {%0,%1,%2,%3}, [%4];"
                 : "=r"(r[0]), "=r"(r[1]), "=r"(r[2]), "=r"(r[3]) : "r"(a));
}

__device__ __forceinline__ void mma16816(float* c, const uint32_t* A, const uint32_t* Bv) {
    asm volatile(
        "mma.sync.aligned.m16n8k16.row.col.f32.bf16.bf16.f32 "
        "{%0,%1,%2,%3}, {%4,%5,%6,%7}, {%8,%9}, {%0,%1,%2,%3};"
        : "+f"(c[0]), "+f"(c[1]), "+f"(c[2]), "+f"(c[3])
        : "r"(A[0]), "r"(A[1]), "r"(A[2]), "r"(A[3]), "r"(Bv[0]), "r"(Bv[1]));
}

__device__ __forceinline__ void cp16(uint32_t dst, const void* src) {
    asm volatile("cp.async.cg.shared.global [%0], [%1], 16;" :: "r"(dst), "l"(src));
}
#define CP_COMMIT() asm volatile("cp.async.commit_group;" ::: "memory")
#define CP_WAIT0()  asm volatile("cp.async.wait_group 0;" ::: "memory")

// pack two fp32 -> bf16x2 {lo=p0, hi=p1}
__device__ __forceinline__ uint32_t pack_bf16(float p0, float p1) {
    uint32_t r;
    asm("cvt.rn.bf16x2.f32 %0, %1, %2;" : "=r"(r) : "f"(p1), "f"(p0));
    return r;
}

// split pair into hi bf16x2 + residual bf16x2
__device__ __forceinline__ void mk2(float p0, float p1, uint32_t& hi, uint32_t& lo) {
    uint32_t h = pack_bf16(p0, p1);
    float r0 = p0 - __uint_as_float(h << 16);
    float r1 = p1 - __uint_as_float(h & 0xffff0000u);
    hi = h;
    lo = pack_bf16(r0, r1);
}

__device__ __forceinline__ void split2(float x, unsigned short& hh, unsigned short& ll) {
    __nv_bfloat16 hb = __float2bfloat16(x);
    hh = reinterpret_cast<unsigned short&>(hb);
    float r = x - __bfloat162float(hb);
    __nv_bfloat16 lb = __float2bfloat16(r);
    ll = reinterpret_cast<unsigned short&>(lb);
}

// ---------------------------------------------------------------------------
// Prep kernels
// ---------------------------------------------------------------------------
__global__ void __launch_bounds__(256) pack_split_kernel(
    const float* __restrict__ src, unsigned short* __restrict__ hi,
    unsigned short* __restrict__ lo)
{
    int i = blockIdx.x * 256 + threadIdx.x;
    float4 v = ((const float4*)src)[i];
    unsigned short h[4], l[4];
    split2(v.x, h[0], l[0]); split2(v.y, h[1], l[1]);
    split2(v.z, h[2], l[2]); split2(v.w, h[3], l[3]);
    ((uint2*)hi)[i] = make_uint2((uint32_t)h[0] | ((uint32_t)h[1] << 16),
                                 (uint32_t)h[2] | ((uint32_t)h[3] << 16));
    ((uint2*)lo)[i] = make_uint2((uint32_t)l[0] | ((uint32_t)l[1] << 16),
                                 (uint32_t)l[2] | ((uint32_t)l[3] << 16));
}

__global__ void __launch_bounds__(256) transpose_pack_kernel(
    const float* __restrict__ w, unsigned short* __restrict__ th,
    unsigned short* __restrict__ tl, int K, int N)
{
    __shared__ float tile[32][33];
    const int k0 = blockIdx.y * 32, n0 = blockIdx.x * 32;
    const int tx = threadIdx.x, ty = threadIdx.y;   // 32 x 8
    #pragma unroll
    for (int i = 0; i < 32; i += 8)
        tile[ty + i][tx] = w[(size_t)(k0 + ty + i) * N + n0 + tx];
    __syncthreads();
    #pragma unroll
    for (int i = 0; i < 32; i += 8) {
        int n = n0 + ty + i;
        int k = k0 + tx;
        float v = tile[tx][ty + i];
        unsigned short hh, ll;
        split2(v, hh, ll);
        th[(size_t)n * K + k] = hh;
        tl[(size_t)n * K + k] = ll;
    }
}

// ---------------------------------------------------------------------------
// Split-bf16 mma.sync GEMM: out = A @ B^T + bias.  (R6 version — measured best)
// BM=BN=128, BK=32, 8 warps (2x4), warp tile 64x32, 2-stage cp.async.
// ---------------------------------------------------------------------------
#define GEMM_SMEM 65536

__global__ void __launch_bounds__(256) gemm_mma_kernel(
    const unsigned short* __restrict__ ah, const unsigned short* __restrict__ al,
    const unsigned short* __restrict__ bh, const unsigned short* __restrict__ bl,
    const float* __restrict__ bias, float* __restrict__ outf,
    unsigned short* __restrict__ outh, unsigned short* __restrict__ outl,
    int M, int N, int K)
{
    extern __shared__ char smc[];
    const uint32_t sbase = smem_u32(smc);
    const int tid  = threadIdx.x;
    const int wid  = tid >> 5, lane = tid & 31;
    const int wm   = wid >> 2, wn = wid & 3;
    const int mBase = blockIdx.y * 128;
    const int nBase = blockIdx.x * 128;
    const int nk = K >> 5;

    const int r0c = tid >> 2;
    const int c0c = tid & 3;
    auto sw = [](int r, int c) { return r * 64 + ((c ^ ((r >> 1) & 3)) << 4); };

    auto issue = [&](int ks, int stage) {
        const int kb = ks << 5;
        const unsigned short* gs[4] = { ah, al, bh, bl };
        #pragma unroll
        for (int part = 0; part < 4; part++) {
            const unsigned short* g = gs[part] +
                (size_t)((part < 2) ? mBase : nBase) * K + kb;
            uint32_t pb = sbase + stage * 32768 + part * 8192;
            cp16(pb + sw(r0c,      c0c), g + (size_t)r0c        * K + c0c * 8);
            cp16(pb + sw(r0c + 64, c0c), g + (size_t)(r0c + 64) * K + c0c * 8);
        }
        CP_COMMIT();
    };

    float acc[4][4][4];
    #pragma unroll
    for (int i = 0; i < 4; i++)
        #pragma unroll
        for (int j = 0; j < 4; j++)
            #pragma unroll
            for (int r = 0; r < 4; r++) acc[i][j][r] = 0.f;

    const int la_row = lane & 15;
    const int la_kh  = lane >> 4;
    const int lb_row = lane & 7;
    const int lb_kh  = (lane >> 3) & 1;

    issue(0, 0);

    for (int ks = 0; ks < nk; ks++) {
        const int cur = ks & 1;
        CP_WAIT0();
        __syncthreads();
        if (ks + 1 < nk) issue(ks + 1, cur ^ 1);

        const uint32_t sAh = sbase + cur * 32768;
        const uint32_t sAl = sAh + 8192;
        const uint32_t sBh = sAh + 16384;
        const uint32_t sBl = sAh + 24576;

        #pragma unroll
        for (int kk = 0; kk < 2; kk++) {
            uint32_t Af[4][4], Bf[4][2];
            const int ch_a = kk * 2 + la_kh;
            const int ch_b = kk * 2 + lb_kh;

            #pragma unroll
            for (int i = 0; i < 4; i++) {
                int row = wm * 64 + i * 16 + la_row;
                ldsm_x4(Af[i][0], Af[i][1], Af[i][2], Af[i][3], sAh + sw(row, ch_a));
            }
            #pragma unroll
            for (int j = 0; j < 4; j++) {
                int row = wn * 32 + j * 8 + lb_row;
                ldsm_x2(Bf[j][0], Bf[j][1], sBh + sw(row, ch_b));
            }
            #pragma unroll
            for (int i = 0; i < 4; i++)
                #pragma unroll
                for (int j = 0; j < 4; j++) mma16816(acc[i][j], Af[i], Bf[j]);

            #pragma unroll
            for (int j = 0; j < 4; j++) {
                int row = wn * 32 + j * 8 + lb_row;
                ldsm_x2(Bf[j][0], Bf[j][1], sBl + sw(row, ch_b));
            }
            #pragma unroll
            for (int i = 0; i < 4; i++)
                #pragma unroll
                for (int j = 0; j < 4; j++) mma16816(acc[i][j], Af[i], Bf[j]);

            #pragma unroll
            for (int i = 0; i < 4; i++) {
                int row = wm * 64 + i * 16 + la_row;
                ldsm_x4(Af[i][0], Af[i][1], Af[i][2], Af[i][3], sAl + sw(row, ch_a));
            }
            #pragma unroll
            for (int j = 0; j < 4; j++) {
                int row = wn * 32 + j * 8 + lb_row;
                ldsm_x2(Bf[j][0], Bf[j][1], sBh + sw(row, ch_b));
            }
            #pragma unroll
            for (int i = 0; i < 4; i++)
                #pragma unroll
                for (int j = 0; j < 4; j++) mma16816(acc[i][j], Af[i], Bf[j]);
        }
    }

    // Epilogue
    const int g = lane >> 2, q = lane & 3;
    #pragma unroll
    for (int i = 0; i < 4; i++) {
        const int row0 = mBase + wm * 64 + i * 16 + g;
        #pragma unroll
        for (int j = 0; j < 4; j++) {
            const int col = nBase + wn * 32 + j * 8 + q * 2;
            float2 bb = *(const float2*)(bias + col);
            float v0x = acc[i][j][0] + bb.x, v0y = acc[i][j][1] + bb.y;
            float v1x = acc[i][j][2] + bb.x, v1y = acc[i][j][3] + bb.y;
            if (outh) {
                uint32_t h0, l0, h1, l1;
                mk2(v0x, v0y, h0, l0);
                mk2(v1x, v1y, h1, l1);
                *(uint32_t*)(outh + (size_t)row0 * N + col)       = h0;
                *(uint32_t*)(outl + (size_t)row0 * N + col)       = l0;
                *(uint32_t*)(outh + (size_t)(row0 + 8) * N + col) = h1;
                *(uint32_t*)(outl + (size_t)(row0 + 8) * N + col) = l1;
            } else {
                *(float2*)(outf + (size_t)row0 * N + col)       = make_float2(v0x, v0y);
                *(float2*)(outf + (size_t)(row0 + 8) * N + col) = make_float2(v1x, v1y);
            }
        }
    }
}

// ---------------------------------------------------------------------------
// Tensor-core flash attention (causal, split-bf16).
// Block = 128 q rows of one (b,h), 8 warps (m16 each), 256 threads.
// 2-stage K/V cp.async pipeline, single barrier per tile, 96KB smem,
// __launch_bounds__(256,2) -> target 2 CTAs/SM for latency hiding.
// ---------------------------------------------------------------------------
#define ATTN_SMEM (32768 + 2*32768)

__global__ void __launch_bounds__(256, 2) attn_mma_kernel(
    const unsigned short* __restrict__ qkvh,
    const unsigned short* __restrict__ qkvl,
    unsigned short* __restrict__ atth,
    unsigned short* __restrict__ attl)
{
    extern __shared__ char smc[];
    const uint32_t sb = smem_u32(smc);
    const int tid = threadIdx.x, lane = tid & 31, w = tid >> 5;
    const int bh = blockIdx.y, b = bh >> 4, hd = bh & 15;
    const int qb = (int)gridDim.x - 1 - (int)blockIdx.x;   // big blocks first
    const int q0 = qb * 128;
    const int nkt = 2 * qb + 2;

    const size_t base = (size_t)b * T_ * 3072 + hd * 64;
    const unsigned short* qh = qkvh + base;
    const unsigned short* qlp = qkvl + base;
    const unsigned short* kh = qh + 1024;
    const unsigned short* kl = qlp + 1024;
    const unsigned short* vh = qh + 2048;
    const unsigned short* vl = qlp + 2048;

    const uint32_t sQh = sb, sQl = sb + 16384;
    auto stage0 = [&](int s) { return sb + 32768 + s * 32768; };
    auto off = [](int r, int c) { return r * 128 + ((c ^ (r & 7)) << 4); };

    auto issue_kv = [&](int kt, int s) {
        uint32_t sn = stage0(s);
        const size_t kb = (size_t)kt * 64;
        #pragma unroll
        for (int i = 0; i < 2; i++) {
            int idx = i * 256 + tid;
            int r = idx >> 3, c = idx & 7;
            const size_t g = (kb + r) * 3072 + c * 8;
            cp16(sn +         off(r, c), kh + g);
            cp16(sn + 8192 +  off(r, c), kl + g);
            cp16(sn + 16384 + off(r, c), vh + g);
            cp16(sn + 24576 + off(r, c), vl + g);
        }
        CP_COMMIT();
    };

    // prologue: group0 = Q + K/V tile 0
    #pragma unroll
    for (int i = 0; i < 4; i++) {
        int idx = i * 256 + tid;
        int r = idx >> 3, c = idx & 7;
        const size_t g = (size_t)(q0 + r) * 3072 + c * 8;
        cp16(sQh + off(r, c), qh + g);
        cp16(sQl + off(r, c), qlp + g);
    }
    issue_kv(0, 0);   // commits Q + tile0 together

    float O[8][4], s[8][4];
    #pragma unroll
    for (int j = 0; j < 8; j++) { O[j][0] = O[j][1] = O[j][2] = O[j][3] = 0.f; }
    float m_lo = -1e30f, m_hi = -1e30f, l_lo = 0.f, l_hi = 0.f;

    const int la_row = lane & 15, la_kh = lane >> 4;
    const int kb_row = ((lane >> 4) << 3) + (lane & 7);
    const int kb_ch  = (lane >> 3) & 1;
    const int vb_row = (((lane >> 3) & 1) << 3) + (lane & 7);
    const int vb_ch  = lane >> 4;
    const int rowq_lo = q0 + w * 16 + (lane >> 2);

    for (int kt = 0; kt < nkt; kt++) {
        const int cur = kt & 1;
        CP_WAIT0();
        __syncthreads();
        if (kt + 1 < nkt) issue_kv(kt + 1, cur ^ 1);

        const int k0 = kt * 64;
        const bool active = (k0 <= q0 + w * 16 + 15);
        if (active) {
            const uint32_t cK  = stage0(cur);
            const uint32_t cKl = cK + 8192;
            const uint32_t cV  = cK + 16384;
            const uint32_t cVl = cK + 24576;

            // ---- S = Q K^T (split: QhKh + QlKh + QhKl) ----
            #pragma unroll
            for (int j = 0; j < 8; j++) { s[j][0] = s[j][1] = s[j][2] = s[j][3] = 0.f; }
            #pragma unroll
            for (int kk = 0; kk < 4; kk++) {
                uint32_t aqh[4], aql[4];
                ldsm_x4(aqh[0], aqh[1], aqh[2], aqh[3],
                        sQh + off(w * 16 + la_row, 2 * kk + la_kh));
                ldsm_x4(aql[0], aql[1], aql[2], aql[3],
                        sQl + off(w * 16 + la_row, 2 * kk + la_kh));
                #pragma unroll
                for (int j2 = 0; j2 < 4; j2++) {
                    uint32_t bk[4];
                    ldsm_x4(bk[0], bk[1], bk[2], bk[3],
                            cK + off(16 * j2 + kb_row, 2 * kk + kb_ch));
                    mma16816(s[2 * j2],     aqh, bk);
                    mma16816(s[2 * j2 + 1], aqh, bk + 2);
                    mma16816(s[2 * j2],     aql, bk);
                    mma16816(s[2 * j2 + 1], aql, bk + 2);
                    ldsm_x4(bk[0], bk[1], bk[2], bk[3],
                            cKl + off(16 * j2 + kb_row, 2 * kk + kb_ch));
                    mma16816(s[2 * j2],     aqh, bk);
                    mma16816(s[2 * j2 + 1], aqh, bk + 2);
                }
            }

            // ---- online softmax ----
            const bool masked = (k0 + 63 > q0 + w * 16);
            float rm_lo = -1e30f, rm_hi = -1e30f;
            #pragma unroll
            for (int j = 0; j < 8; j++) {
                int colb = k0 + 8 * j + 2 * (lane & 3);
                #pragma unroll
                for (int e = 0; e < 2; e++) {
                    float v = s[j][e] * 0.125f;
                    if (masked && (colb + e) > rowq_lo) v = -1e30f;
                    s[j][e] = v; rm_lo = fmaxf(rm_lo, v);
                    float v2 = s[j][2 + e] * 0.125f;
                    if (masked && (colb + e) > rowq_lo + 8) v2 = -1e30f;
                    s[j][2 + e] = v2; rm_hi = fmaxf(rm_hi, v2);
                }
            }
            rm_lo = fmaxf(rm_lo, __shfl_xor_sync(0xffffffffu, rm_lo, 1));
            rm_lo = fmaxf(rm_lo, __shfl_xor_sync(0xffffffffu, rm_lo, 2));
            rm_hi = fmaxf(rm_hi, __shfl_xor_sync(0xffffffffu, rm_hi, 1));
            rm_hi = fmaxf(rm_hi, __shfl_xor_sync(0xffffffffu, rm_hi, 2));
            float mn_lo = fmaxf(m_lo, rm_lo), mn_hi = fmaxf(m_hi, rm_hi);
            float corr_lo = __expf(m_lo - mn_lo), corr_hi = __expf(m_hi - mn_hi);
            m_lo = mn_lo; m_hi = mn_hi;
            float ps_lo = 0.f, ps_hi = 0.f;
            #pragma unroll
            for (int j = 0; j < 8; j++) {
                s[j][0] = __expf(s[j][0] - mn_lo);
                s[j][1] = __expf(s[j][1] - mn_lo);
                s[j][2] = __expf(s[j][2] - mn_hi);
                s[j][3] = __expf(s[j][3] - mn_hi);
                ps_lo += s[j][0] + s[j][1];
                ps_hi += s[j][2] + s[j][3];
            }
            ps_lo += __shfl_xor_sync(0xffffffffu, ps_lo, 1);
            ps_lo += __shfl_xor_sync(0xffffffffu, ps_lo, 2);
            ps_hi += __shfl_xor_sync(0xffffffffu, ps_hi, 1);
            ps_hi += __shfl_xor_sync(0xffffffffu, ps_hi, 2);
            l_lo = l_lo * corr_lo + ps_lo;
            l_hi = l_hi * corr_hi + ps_hi;
            #pragma unroll
            for (int j = 0; j < 8; j++) {
                O[j][0] *= corr_lo; O[j][1] *= corr_lo;
                O[j][2] *= corr_hi; O[j][3] *= corr_hi;
            }

            // ---- O += P V (split: PhVh + PlVh + PhVl) ----
            #pragma unroll
            for (int t = 0; t < 4; t++) {
                uint32_t ph[4], pl[4];
                mk2(s[2 * t][0],     s[2 * t][1],     ph[0], pl[0]);
                mk2(s[2 * t][2],     s[2 * t][3],     ph[1], pl[1]);
                mk2(s[2 * t + 1][0], s[2 * t + 1][1], ph[2], pl[2]);
                mk2(s[2 * t + 1][2], s[2 * t + 1][3], ph[3], pl[3]);
                #pragma unroll
                for (int j2 = 0; j2 < 4; j2++) {
                    uint32_t bv[4];
                    ldsm_x4t(bv, cV + off(16 * t + vb_row, 2 * j2 + vb_ch));
                    mma16816(O[2 * j2],     ph, bv);
                    mma16816(O[2 * j2 + 1], ph, bv + 2);
                    mma16816(O[2 * j2],     pl, bv);
                    mma16816(O[2 * j2 + 1], pl, bv + 2);
                    ldsm_x4t(bv, cVl + off(16 * t + vb_row, 2 * j2 + vb_ch));
                    mma16816(O[2 * j2],     ph, bv);
                    mma16816(O[2 * j2 + 1], ph, bv + 2);
                }
            }
        }
    }

    // ---- epilogue: normalize, split-bf16, write ----
    const float inv_lo = 1.f / l_lo, inv_hi = 1.f / l_hi;
    const size_t row_lo = (size_t)(b * T_) + q0 + w * 16 + (lane >> 2);
    const int colb = hd * 64 + 2 * (lane & 3);
    #pragma unroll
    for (int j = 0; j < 8; j++) {
        const int col = colb + 8 * j;
        uint32_t h0, l0, h1, l1;
        mk2(O[j][0] * inv_lo, O[j][1] * inv_lo, h0, l0);
        mk2(O[j][2] * inv_hi, O[j][3] * inv_hi, h1, l1);
        *(uint32_t*)(atth + row_lo * C_ + col)       = h0;
        *(uint32_t*)(attl + row_lo * C_ + col)       = l0;
        *(uint32_t*)(atth + (row_lo + 8) * C_ + col) = h1;
        *(uint32_t*)(attl + (row_lo + 8) * C_ + col) = l1;
    }
}

// ---------------------------------------------------------------------------
extern "C" void kernel_launch(void* const* d_in, const int* in_sizes, int n_in,
                              void* d_out, int out_size)
{
    const float* x      = (const float*)d_in[0];
    const float* w_qkv  = (const float*)d_in[1];
    const float* b_qkv  = (const float*)d_in[2];
    const float* w_proj = (const float*)d_in[3];
    const float* b_proj = (const float*)d_in[4];
    float* out = (float*)d_out;

    unsigned short *qvh, *qvl, *xh, *xl, *wqh, *wql, *wph, *wpl, *ath, *atl;
    cudaGetSymbolAddress((void**)&qvh, g_qkvh);
    cudaGetSymbolAddress((void**)&qvl, g_qkvl);
    cudaGetSymbolAddress((void**)&xh, g_xh);
    cudaGetSymbolAddress((void**)&xl, g_xl);
    cudaGetSymbolAddress((void**)&wqh, g_wqkvh);
    cudaGetSymbolAddress((void**)&wql, g_wqkvl);
    cudaGetSymbolAddress((void**)&wph, g_wprojh);
    cudaGetSymbolAddress((void**)&wpl, g_wprojl);
    cudaGetSymbolAddress((void**)&ath, g_atth);
    cudaGetSymbolAddress((void**)&atl, g_attl);

    cudaFuncSetAttribute(gemm_mma_kernel,
                         cudaFuncAttributeMaxDynamicSharedMemorySize, GEMM_SMEM);
    cudaFuncSetAttribute(attn_mma_kernel,
                         cudaFuncAttributeMaxDynamicSharedMemorySize, ATTN_SMEM);

    // 0) pack inputs to split bf16
    pack_split_kernel<<<M_*C_/1024, 256>>>(x, xh, xl);
    transpose_pack_kernel<<<dim3(3*C_/32, C_/32), dim3(32, 8)>>>(w_qkv, wqh, wql, C_, 3*C_);
    transpose_pack_kernel<<<dim3(C_/32, C_/32), dim3(32, 8)>>>(w_proj, wph, wpl, C_, C_);

    // 1) qkv = x @ w_qkv + b_qkv  -> split-bf16 qkv
    gemm_mma_kernel<<<dim3(3*C_/128, M_/128), 256, GEMM_SMEM>>>(
        xh, xl, wqh, wql, b_qkv, nullptr, qvh, qvl, M_, 3*C_, C_);

    // 2) tensor-core causal flash attention -> split-bf16 att
    attn_mma_kernel<<<dim3(T_/128, B_*H_), 256, ATTN_SMEM>>>(qvh, qvl, ath, atl);

    // 3) out = att @ w_proj + b_proj  -> fp32
    gemm_mma_kernel<<<dim3(C_/128, M_/128), 256, GEMM_SMEM>>>(
        ath, atl, wph, wpl, b_proj, out, nullptr, nullptr, M_, C_, C_);
}

// round 9
// speedup vs baseline: 1.1441x; 1.1208x over previous
#include <cuda_runtime.h>
#include <cuda_bf16.h>
#include <cuda_fp16.h>
#include <stdint.h>
#include <math.h>

#define B_ 4
#define T_ 2048
#define C_ 1024
#define H_ 16
#define D_ 64
#define M_ (B_*T_)   // 8192

// ---------------------------------------------------------------------------
// Scratch (allocation-free __device__ globals)
// ---------------------------------------------------------------------------
__device__ unsigned short g_qkvh[25165824];    // qkv hi fp16 [8192][3072]
__device__ unsigned short g_qkvl[25165824];    // qkv lo fp16
__device__ unsigned short g_xh[8388608];       // x hi bf16 [8192][1024]
__device__ unsigned short g_xl[8388608];
__device__ unsigned short g_wqkvh[3145728];    // w_qkv^T hi bf16 [3072][1024]
__device__ unsigned short g_wqkvl[3145728];
__device__ unsigned short g_wprojh[1048576];   // w_proj^T hi bf16 [1024][1024]
__device__ unsigned short g_wprojl[1048576];
__device__ unsigned short g_atth[8388608];     // attention out hi bf16 [8192][1024]
__device__ unsigned short g_attl[8388608];

// ---------------------------------------------------------------------------
// Helpers (sm_103 baseline: ldmatrix, mma.sync, cp.async)
// ---------------------------------------------------------------------------
__device__ __forceinline__ uint32_t smem_u32(const void* p) {
    uint32_t a;
    asm("{ .reg .u64 t; cvta.to.shared.u64 t, %1; cvt.u32.u64 %0, t; }"
        : "=r"(a) : "l"(p));
    return a;
}

__device__ __forceinline__ void ldsm_x4(uint32_t& r0, uint32_t& r1,
                                        uint32_t& r2, uint32_t& r3, uint32_t a) {
    asm volatile("ldmatrix.sync.aligned.m8n8.x4.shared.b16 {%0,%1,%2,%3}, [%4];"
                 : "=r"(r0), "=r"(r1), "=r"(r2), "=r"(r3) : "r"(a));
}

__device__ __forceinline__ void ldsm_x2(uint32_t& r0, uint32_t& r1, uint32_t a) {
    asm volatile("ldmatrix.sync.aligned.m8n8.x2.shared.b16 {%0,%1}, [%2];"
                 : "=r"(r0), "=r"(r1) : "r"(a));
}

__device__ __forceinline__ void ldsm_x4t(uint32_t* r, uint32_t a) {
    asm volatile("ldmatrix.sync.aligned.m8n8.x4.trans.shared.b16 {%0,%1,%2,%3}, [%4];"
                 : "=r"(r[0]), "=r"(r[1]), "=r"(r[2]), "=r"(r[3]) : "r"(a));
}

// bf16 MMA (GEMMs)
__device__ __forceinline__ void mma16816(float* c, const uint32_t* A, const uint32_t* Bv) {
    asm volatile(
        "mma.sync.aligned.m16n8k16.row.col.f32.bf16.bf16.f32 "
        "{%0,%1,%2,%3}, {%4,%5,%6,%7}, {%8,%9}, {%0,%1,%2,%3};"
        : "+f"(c[0]), "+f"(c[1]), "+f"(c[2]), "+f"(c[3])
        : "r"(A[0]), "r"(A[1]), "r"(A[2]), "r"(A[3]), "r"(Bv[0]), "r"(Bv[1]));
}

// fp16 MMA (attention)
__device__ __forceinline__ void mma16816h(float* c, const uint32_t* A, const uint32_t* Bv) {
    asm volatile(
        "mma.sync.aligned.m16n8k16.row.col.f32.f16.f16.f32 "
        "{%0,%1,%2,%3}, {%4,%5,%6,%7}, {%8,%9}, {%0,%1,%2,%3};"
        : "+f"(c[0]), "+f"(c[1]), "+f"(c[2]), "+f"(c[3])
        : "r"(A[0]), "r"(A[1]), "r"(A[2]), "r"(A[3]), "r"(Bv[0]), "r"(Bv[1]));
}

__device__ __forceinline__ void cp16(uint32_t dst, const void* src) {
    asm volatile("cp.async.cg.shared.global [%0], [%1], 16;" :: "r"(dst), "l"(src));
}
#define CP_COMMIT() asm volatile("cp.async.commit_group;" ::: "memory")
#define CP_WAIT0()  asm volatile("cp.async.wait_group 0;" ::: "memory")

// pack two fp32 -> bf16x2 {lo=p0, hi=p1}
__device__ __forceinline__ uint32_t pack_bf16(float p0, float p1) {
    uint32_t r;
    asm("cvt.rn.bf16x2.f32 %0, %1, %2;" : "=r"(r) : "f"(p1), "f"(p0));
    return r;
}

// pack two fp32 -> f16x2 {lo=p0, hi=p1}
__device__ __forceinline__ uint32_t pack_f16(float p0, float p1) {
    uint32_t r;
    asm("cvt.rn.f16x2.f32 %0, %1, %2;" : "=r"(r) : "f"(p1), "f"(p0));
    return r;
}

// split pair -> bf16x2 hi + bf16x2 residual
__device__ __forceinline__ void mk2(float p0, float p1, uint32_t& hi, uint32_t& lo) {
    uint32_t h = pack_bf16(p0, p1);
    float r0 = p0 - __uint_as_float(h << 16);
    float r1 = p1 - __uint_as_float(h & 0xffff0000u);
    hi = h;
    lo = pack_bf16(r0, r1);
}

// split pair -> f16x2 hi + f16x2 residual
__device__ __forceinline__ void mk2h(float p0, float p1, uint32_t& hi, uint32_t& lo) {
    uint32_t h = pack_f16(p0, p1);
    __half2 hh = *reinterpret_cast<__half2*>(&h);
    float r0 = p0 - __low2float(hh);
    float r1 = p1 - __high2float(hh);
    hi = h;
    lo = pack_f16(r0, r1);
}

__device__ __forceinline__ void split2(float x, unsigned short& hh, unsigned short& ll) {
    __nv_bfloat16 hb = __float2bfloat16(x);
    hh = reinterpret_cast<unsigned short&>(hb);
    float r = x - __bfloat162float(hb);
    __nv_bfloat16 lb = __float2bfloat16(r);
    ll = reinterpret_cast<unsigned short&>(lb);
}

// ---------------------------------------------------------------------------
// Prep kernels
// ---------------------------------------------------------------------------
__global__ void __launch_bounds__(256) pack_split_kernel(
    const float* __restrict__ src, unsigned short* __restrict__ hi,
    unsigned short* __restrict__ lo)
{
    int i = blockIdx.x * 256 + threadIdx.x;
    float4 v = ((const float4*)src)[i];
    unsigned short h[4], l[4];
    split2(v.x, h[0], l[0]); split2(v.y, h[1], l[1]);
    split2(v.z, h[2], l[2]); split2(v.w, h[3], l[3]);
    ((uint2*)hi)[i] = make_uint2((uint32_t)h[0] | ((uint32_t)h[1] << 16),
                                 (uint32_t)h[2] | ((uint32_t)h[3] << 16));
    ((uint2*)lo)[i] = make_uint2((uint32_t)l[0] | ((uint32_t)l[1] << 16),
                                 (uint32_t)l[2] | ((uint32_t)l[3] << 16));
}

__global__ void __launch_bounds__(256) transpose_pack_kernel(
    const float* __restrict__ w, unsigned short* __restrict__ th,
    unsigned short* __restrict__ tl, int K, int N)
{
    __shared__ float tile[32][33];
    const int k0 = blockIdx.y * 32, n0 = blockIdx.x * 32;
    const int tx = threadIdx.x, ty = threadIdx.y;   // 32 x 8
    #pragma unroll
    for (int i = 0; i < 32; i += 8)
        tile[ty + i][tx] = w[(size_t)(k0 + ty + i) * N + n0 + tx];
    __syncthreads();
    #pragma unroll
    for (int i = 0; i < 32; i += 8) {
        int n = n0 + ty + i;
        int k = k0 + tx;
        float v = tile[tx][ty + i];
        unsigned short hh, ll;
        split2(v, hh, ll);
        th[(size_t)n * K + k] = hh;
        tl[(size_t)n * K + k] = ll;
    }
}

// ---------------------------------------------------------------------------
// Split-bf16 mma.sync GEMM: out = A @ B^T + bias.  (measured-best structure)
// halfout: 0 -> split-bf16 out, 1 -> split-fp16 out (for attention inputs)
// ---------------------------------------------------------------------------
#define GEMM_SMEM 65536

__global__ void __launch_bounds__(256) gemm_mma_kernel(
    const unsigned short* __restrict__ ah, const unsigned short* __restrict__ al,
    const unsigned short* __restrict__ bh, const unsigned short* __restrict__ bl,
    const float* __restrict__ bias, float* __restrict__ outf,
    unsigned short* __restrict__ outh, unsigned short* __restrict__ outl,
    int M, int N, int K, int halfout)
{
    extern __shared__ char smc[];
    const uint32_t sbase = smem_u32(smc);
    const int tid  = threadIdx.x;
    const int wid  = tid >> 5, lane = tid & 31;
    const int wm   = wid >> 2, wn = wid & 3;
    const int mBase = blockIdx.y * 128;
    const int nBase = blockIdx.x * 128;
    const int nk = K >> 5;

    const int r0c = tid >> 2;
    const int c0c = tid & 3;
    auto sw = [](int r, int c) { return r * 64 + ((c ^ ((r >> 1) & 3)) << 4); };

    auto issue = [&](int ks, int stage) {
        const int kb = ks << 5;
        const unsigned short* gs[4] = { ah, al, bh, bl };
        #pragma unroll
        for (int part = 0; part < 4; part++) {
            const unsigned short* g = gs[part] +
                (size_t)((part < 2) ? mBase : nBase) * K + kb;
            uint32_t pb = sbase + stage * 32768 + part * 8192;
            cp16(pb + sw(r0c,      c0c), g + (size_t)r0c        * K + c0c * 8);
            cp16(pb + sw(r0c + 64, c0c), g + (size_t)(r0c + 64) * K + c0c * 8);
        }
        CP_COMMIT();
    };

    float acc[4][4][4];
    #pragma unroll
    for (int i = 0; i < 4; i++)
        #pragma unroll
        for (int j = 0; j < 4; j++)
            #pragma unroll
            for (int r = 0; r < 4; r++) acc[i][j][r] = 0.f;

    const int la_row = lane & 15;
    const int la_kh  = lane >> 4;
    const int lb_row = lane & 7;
    const int lb_kh  = (lane >> 3) & 1;

    issue(0, 0);

    for (int ks = 0; ks < nk; ks++) {
        const int cur = ks & 1;
        CP_WAIT0();
        __syncthreads();
        if (ks + 1 < nk) issue(ks + 1, cur ^ 1);

        const uint32_t sAh = sbase + cur * 32768;
        const uint32_t sAl = sAh + 8192;
        const uint32_t sBh = sAh + 16384;
        const uint32_t sBl = sAh + 24576;

        #pragma unroll
        for (int kk = 0; kk < 2; kk++) {
            uint32_t Af[4][4], Bf[4][2];
            const int ch_a = kk * 2 + la_kh;
            const int ch_b = kk * 2 + lb_kh;

            #pragma unroll
            for (int i = 0; i < 4; i++) {
                int row = wm * 64 + i * 16 + la_row;
                ldsm_x4(Af[i][0], Af[i][1], Af[i][2], Af[i][3], sAh + sw(row, ch_a));
            }
            #pragma unroll
            for (int j = 0; j < 4; j++) {
                int row = wn * 32 + j * 8 + lb_row;
                ldsm_x2(Bf[j][0], Bf[j][1], sBh + sw(row, ch_b));
            }
            #pragma unroll
            for (int i = 0; i < 4; i++)
                #pragma unroll
                for (int j = 0; j < 4; j++) mma16816(acc[i][j], Af[i], Bf[j]);

            #pragma unroll
            for (int j = 0; j < 4; j++) {
                int row = wn * 32 + j * 8 + lb_row;
                ldsm_x2(Bf[j][0], Bf[j][1], sBl + sw(row, ch_b));
            }
            #pragma unroll
            for (int i = 0; i < 4; i++)
                #pragma unroll
                for (int j = 0; j < 4; j++) mma16816(acc[i][j], Af[i], Bf[j]);

            #pragma unroll
            for (int i = 0; i < 4; i++) {
                int row = wm * 64 + i * 16 + la_row;
                ldsm_x4(Af[i][0], Af[i][1], Af[i][2], Af[i][3], sAl + sw(row, ch_a));
            }
            #pragma unroll
            for (int j = 0; j < 4; j++) {
                int row = wn * 32 + j * 8 + lb_row;
                ldsm_x2(Bf[j][0], Bf[j][1], sBh + sw(row, ch_b));
            }
            #pragma unroll
            for (int i = 0; i < 4; i++)
                #pragma unroll
                for (int j = 0; j < 4; j++) mma16816(acc[i][j], Af[i], Bf[j]);
        }
    }

    // Epilogue
    const int g = lane >> 2, q = lane & 3;
    #pragma unroll
    for (int i = 0; i < 4; i++) {
        const int row0 = mBase + wm * 64 + i * 16 + g;
        #pragma unroll
        for (int j = 0; j < 4; j++) {
            const int col = nBase + wn * 32 + j * 8 + q * 2;
            float2 bb = *(const float2*)(bias + col);
            float v0x = acc[i][j][0] + bb.x, v0y = acc[i][j][1] + bb.y;
            float v1x = acc[i][j][2] + bb.x, v1y = acc[i][j][3] + bb.y;
            if (outh) {
                uint32_t h0, l0, h1, l1;
                if (halfout) {
                    mk2h(v0x, v0y, h0, l0);
                    mk2h(v1x, v1y, h1, l1);
                } else {
                    mk2(v0x, v0y, h0, l0);
                    mk2(v1x, v1y, h1, l1);
                }
                *(uint32_t*)(outh + (size_t)row0 * N + col)       = h0;
                *(uint32_t*)(outl + (size_t)row0 * N + col)       = l0;
                *(uint32_t*)(outh + (size_t)(row0 + 8) * N + col) = h1;
                *(uint32_t*)(outl + (size_t)(row0 + 8) * N + col) = l1;
            } else {
                *(float2*)(outf + (size_t)row0 * N + col)       = make_float2(v0x, v0y);
                *(float2*)(outf + (size_t)(row0 + 8) * N + col) = make_float2(v1x, v1y);
            }
        }
    }
}

// ---------------------------------------------------------------------------
// Tensor-core flash attention (causal, fp16).
// S = Qh*Kh + Ql*Kh (fp16 2-term; dropped Q*Kl ~2^-11).
// PV = Ph*Vh + Ph*Vl (P single fp16; V 2-term fp16).
// Block = 128 q rows, 8 warps (m16), 2-stage K/V pipeline (24KB/stage).
// Smem: Qh 16K | Ql 16K | 2 x (Kh 8K | Vh 8K | Vl 8K) = 80KB.
// ---------------------------------------------------------------------------
#define ATTN_SMEM (32768 + 2*24576)

__global__ void __launch_bounds__(256, 2) attn_mma_kernel(
    const unsigned short* __restrict__ qkvh,
    const unsigned short* __restrict__ qkvl,
    unsigned short* __restrict__ atth,
    unsigned short* __restrict__ attl)
{
    extern __shared__ char smc[];
    const uint32_t sb = smem_u32(smc);
    const int tid = threadIdx.x, lane = tid & 31, w = tid >> 5;
    const int bh = blockIdx.y, b = bh >> 4, hd = bh & 15;
    const int qb = (int)gridDim.x - 1 - (int)blockIdx.x;   // big blocks first
    const int q0 = qb * 128;
    const int nkt = 2 * qb + 2;

    const size_t base = (size_t)b * T_ * 3072 + hd * 64;
    const unsigned short* qh = qkvh + base;
    const unsigned short* qlp = qkvl + base;
    const unsigned short* kh = qh + 1024;
    const unsigned short* vh = qh + 2048;
    const unsigned short* vl = qlp + 2048;

    const uint32_t sQh = sb, sQl = sb + 16384;
    auto stage0 = [&](int s) { return sb + 32768 + s * 24576; };
    auto off = [](int r, int c) { return r * 128 + ((c ^ (r & 7)) << 4); };

    auto issue_kv = [&](int kt, int s) {
        uint32_t sn = stage0(s);
        const size_t kb = (size_t)kt * 64;
        #pragma unroll
        for (int i = 0; i < 2; i++) {
            int idx = i * 256 + tid;
            int r = idx >> 3, c = idx & 7;
            const size_t g = (kb + r) * 3072 + c * 8;
            cp16(sn +         off(r, c), kh + g);
            cp16(sn + 8192 +  off(r, c), vh + g);
            cp16(sn + 16384 + off(r, c), vl + g);
        }
        CP_COMMIT();
    };

    // prologue: Q (hi+lo) + K/V tile 0, one commit group
    #pragma unroll
    for (int i = 0; i < 4; i++) {
        int idx = i * 256 + tid;
        int r = idx >> 3, c = idx & 7;
        const size_t g = (size_t)(q0 + r) * 3072 + c * 8;
        cp16(sQh + off(r, c), qh + g);
        cp16(sQl + off(r, c), qlp + g);
    }
    issue_kv(0, 0);

    float O[8][4], s[8][4];
    #pragma unroll
    for (int j = 0; j < 8; j++) { O[j][0] = O[j][1] = O[j][2] = O[j][3] = 0.f; }
    float m_lo = -1e30f, m_hi = -1e30f, l_lo = 0.f, l_hi = 0.f;

    const int la_row = lane & 15, la_kh = lane >> 4;
    const int kb_row = ((lane >> 4) << 3) + (lane & 7);
    const int kb_ch  = (lane >> 3) & 1;
    const int vb_row = (((lane >> 3) & 1) << 3) + (lane & 7);
    const int vb_ch  = lane >> 4;
    const int rowq_lo = q0 + w * 16 + (lane >> 2);
    const float SC = 0.125f * 1.4426950408889634f;   // scale * log2(e)

    for (int kt = 0; kt < nkt; kt++) {
        const int cur = kt & 1;
        CP_WAIT0();
        __syncthreads();
        if (kt + 1 < nkt) issue_kv(kt + 1, cur ^ 1);

        const int k0 = kt * 64;
        const bool active = (k0 <= q0 + w * 16 + 15);
        if (active) {
            const uint32_t cK  = stage0(cur);
            const uint32_t cV  = cK + 8192;
            const uint32_t cVl = cK + 16384;

            // ---- S = Q K^T (fp16 2-term: QhKh + QlKh) ----
            #pragma unroll
            for (int j = 0; j < 8; j++) { s[j][0] = s[j][1] = s[j][2] = s[j][3] = 0.f; }
            #pragma unroll
            for (int kk = 0; kk < 4; kk++) {
                uint32_t aqh[4], aql[4];
                ldsm_x4(aqh[0], aqh[1], aqh[2], aqh[3],
                        sQh + off(w * 16 + la_row, 2 * kk + la_kh));
                ldsm_x4(aql[0], aql[1], aql[2], aql[3],
                        sQl + off(w * 16 + la_row, 2 * kk + la_kh));
                #pragma unroll
                for (int j2 = 0; j2 < 4; j2++) {
                    uint32_t bk[4];
                    ldsm_x4(bk[0], bk[1], bk[2], bk[3],
                            cK + off(16 * j2 + kb_row, 2 * kk + kb_ch));
                    mma16816h(s[2 * j2],     aqh, bk);
                    mma16816h(s[2 * j2 + 1], aqh, bk + 2);
                    mma16816h(s[2 * j2],     aql, bk);
                    mma16816h(s[2 * j2 + 1], aql, bk + 2);
                }
            }

            // ---- online softmax (exp2 domain) ----
            const bool masked = (k0 + 63 > q0 + w * 16);
            float rm_lo = -1e30f, rm_hi = -1e30f;
            #pragma unroll
            for (int j = 0; j < 8; j++) {
                int colb = k0 + 8 * j + 2 * (lane & 3);
                #pragma unroll
                for (int e = 0; e < 2; e++) {
                    float v = s[j][e] * SC;
                    if (masked && (colb + e) > rowq_lo) v = -1e30f;
                    s[j][e] = v; rm_lo = fmaxf(rm_lo, v);
                    float v2 = s[j][2 + e] * SC;
                    if (masked && (colb + e) > rowq_lo + 8) v2 = -1e30f;
                    s[j][2 + e] = v2; rm_hi = fmaxf(rm_hi, v2);
                }
            }
            rm_lo = fmaxf(rm_lo, __shfl_xor_sync(0xffffffffu, rm_lo, 1));
            rm_lo = fmaxf(rm_lo, __shfl_xor_sync(0xffffffffu, rm_lo, 2));
            rm_hi = fmaxf(rm_hi, __shfl_xor_sync(0xffffffffu, rm_hi, 1));
            rm_hi = fmaxf(rm_hi, __shfl_xor_sync(0xffffffffu, rm_hi, 2));
            float mn_lo = fmaxf(m_lo, rm_lo), mn_hi = fmaxf(m_hi, rm_hi);
            float corr_lo = exp2f(m_lo - mn_lo), corr_hi = exp2f(m_hi - mn_hi);
            m_lo = mn_lo; m_hi = mn_hi;
            float ps_lo = 0.f, ps_hi = 0.f;
            #pragma unroll
            for (int j = 0; j < 8; j++) {
                s[j][0] = exp2f(s[j][0] - mn_lo);
                s[j][1] = exp2f(s[j][1] - mn_lo);
                s[j][2] = exp2f(s[j][2] - mn_hi);
                s[j][3] = exp2f(s[j][3] - mn_hi);
                ps_lo += s[j][0] + s[j][1];
                ps_hi += s[j][2] + s[j][3];
            }
            ps_lo += __shfl_xor_sync(0xffffffffu, ps_lo, 1);
            ps_lo += __shfl_xor_sync(0xffffffffu, ps_lo, 2);
            ps_hi += __shfl_xor_sync(0xffffffffu, ps_hi, 1);
            ps_hi += __shfl_xor_sync(0xffffffffu, ps_hi, 2);
            l_lo = l_lo * corr_lo + ps_lo;
            l_hi = l_hi * corr_hi + ps_hi;
            #pragma unroll
            for (int j = 0; j < 8; j++) {
                O[j][0] *= corr_lo; O[j][1] *= corr_lo;
                O[j][2] *= corr_hi; O[j][3] *= corr_hi;
            }

            // ---- O += P V (P fp16 single; V fp16 2-term) ----
            #pragma unroll
            for (int t = 0; t < 4; t++) {
                uint32_t ph[4];
                ph[0] = pack_f16(s[2 * t][0],     s[2 * t][1]);
                ph[1] = pack_f16(s[2 * t][2],     s[2 * t][3]);
                ph[2] = pack_f16(s[2 * t + 1][0], s[2 * t + 1][1]);
                ph[3] = pack_f16(s[2 * t + 1][2], s[2 * t + 1][3]);
                #pragma unroll
                for (int j2 = 0; j2 < 4; j2++) {
                    uint32_t bv[4];
                    ldsm_x4t(bv, cV + off(16 * t + vb_row, 2 * j2 + vb_ch));
                    mma16816h(O[2 * j2],     ph, bv);
                    mma16816h(O[2 * j2 + 1], ph, bv + 2);
                    ldsm_x4t(bv, cVl + off(16 * t + vb_row, 2 * j2 + vb_ch));
                    mma16816h(O[2 * j2],     ph, bv);
                    mma16816h(O[2 * j2 + 1], ph, bv + 2);
                }
            }
        }
    }

    // ---- epilogue: normalize, split-bf16, write ----
    const float inv_lo = 1.f / l_lo, inv_hi = 1.f / l_hi;
    const size_t row_lo = (size_t)(b * T_) + q0 + w * 16 + (lane >> 2);
    const int colb = hd * 64 + 2 * (lane & 3);
    #pragma unroll
    for (int j = 0; j < 8; j++) {
        const int col = colb + 8 * j;
        uint32_t h0, l0, h1, l1;
        mk2(O[j][0] * inv_lo, O[j][1] * inv_lo, h0, l0);
        mk2(O[j][2] * inv_hi, O[j][3] * inv_hi, h1, l1);
        *(uint32_t*)(atth + row_lo * C_ + col)       = h0;
        *(uint32_t*)(attl + row_lo * C_ + col)       = l0;
        *(uint32_t*)(atth + (row_lo + 8) * C_ + col) = h1;
        *(uint32_t*)(attl + (row_lo + 8) * C_ + col) = l1;
    }
}

// ---------------------------------------------------------------------------
extern "C" void kernel_launch(void* const* d_in, const int* in_sizes, int n_in,
                              void* d_out, int out_size)
{
    const float* x      = (const float*)d_in[0];
    const float* w_qkv  = (const float*)d_in[1];
    const float* b_qkv  = (const float*)d_in[2];
    const float* w_proj = (const float*)d_in[3];
    const float* b_proj = (const float*)d_in[4];
    float* out = (float*)d_out;

    unsigned short *qvh, *qvl, *xh, *xl, *wqh, *wql, *wph, *wpl, *ath, *atl;
    cudaGetSymbolAddress((void**)&qvh, g_qkvh);
    cudaGetSymbolAddress((void**)&qvl, g_qkvl);
    cudaGetSymbolAddress((void**)&xh, g_xh);
    cudaGetSymbolAddress((void**)&xl, g_xl);
    cudaGetSymbolAddress((void**)&wqh, g_wqkvh);
    cudaGetSymbolAddress((void**)&wql, g_wqkvl);
    cudaGetSymbolAddress((void**)&wph, g_wprojh);
    cudaGetSymbolAddress((void**)&wpl, g_wprojl);
    cudaGetSymbolAddress((void**)&ath, g_atth);
    cudaGetSymbolAddress((void**)&atl, g_attl);

    cudaFuncSetAttribute(gemm_mma_kernel,
                         cudaFuncAttributeMaxDynamicSharedMemorySize, GEMM_SMEM);
    cudaFuncSetAttribute(attn_mma_kernel,
                         cudaFuncAttributeMaxDynamicSharedMemorySize, ATTN_SMEM);

    // 0) pack inputs to split bf16
    pack_split_kernel<<<M_*C_/1024, 256>>>(x, xh, xl);
    transpose_pack_kernel<<<dim3(3*C_/32, C_/32), dim3(32, 8)>>>(w_qkv, wqh, wql, C_, 3*C_);
    transpose_pack_kernel<<<dim3(C_/32, C_/32), dim3(32, 8)>>>(w_proj, wph, wpl, C_, C_);

    // 1) qkv = x @ w_qkv + b_qkv  -> split-fp16 qkv (for attention)
    gemm_mma_kernel<<<dim3(3*C_/128, M_/128), 256, GEMM_SMEM>>>(
        xh, xl, wqh, wql, b_qkv, nullptr, qvh, qvl, M_, 3*C_, C_, 1);

    // 2) tensor-core causal flash attention (fp16) -> split-bf16 att
    attn_mma_kernel<<<dim3(T_/128, B_*H_), 256, ATTN_SMEM>>>(qvh, qvl, ath, atl);

    // 3) out = att @ w_proj + b_proj  -> fp32
    gemm_mma_kernel<<<dim3(C_/128, M_/128), 256, GEMM_SMEM>>>(
        ath, atl, wph, wpl, b_proj, out, nullptr, nullptr, M_, C_, C_, 0);
}

// round 10
// speedup vs baseline: 1.3450x; 1.1756x over previous
#include <cuda_runtime.h>
#include <cuda_bf16.h>
#include <cuda_fp16.h>
#include <stdint.h>
#include <math.h>

#define B_ 4
#define T_ 2048
#define C_ 1024
#define H_ 16
#define D_ 64
#define M_ (B_*T_)   // 8192

// ---------------------------------------------------------------------------
// Scratch (allocation-free __device__ globals) — all fp16 hi/lo splits
// ---------------------------------------------------------------------------
__device__ unsigned short g_qkvh[25165824];    // qkv hi fp16 [8192][3072]
__device__ unsigned short g_qkvl[25165824];    // qkv lo
__device__ unsigned short g_xh[8388608];       // x hi fp16 [8192][1024]
__device__ unsigned short g_xl[8388608];
__device__ unsigned short g_wqkvh[3145728];    // w_qkv^T hi fp16 [3072][1024]
__device__ unsigned short g_wprojh[1048576];   // w_proj^T hi fp16 [1024][1024]
__device__ unsigned short g_atth[8388608];     // attention out hi fp16 [8192][1024]
__device__ unsigned short g_attl[8388608];

// ---------------------------------------------------------------------------
// Helpers (sm_103 baseline: ldmatrix, mma.sync, cp.async)
// ---------------------------------------------------------------------------
__device__ __forceinline__ uint32_t smem_u32(const void* p) {
    uint32_t a;
    asm("{ .reg .u64 t; cvta.to.shared.u64 t, %1; cvt.u32.u64 %0, t; }"
        : "=r"(a) : "l"(p));
    return a;
}

__device__ __forceinline__ void ldsm_x4(uint32_t& r0, uint32_t& r1,
                                        uint32_t& r2, uint32_t& r3, uint32_t a) {
    asm volatile("ldmatrix.sync.aligned.m8n8.x4.shared.b16 {%0,%1,%2,%3}, [%4];"
                 : "=r"(r0), "=r"(r1), "=r"(r2), "=r"(r3) : "r"(a));
}

__device__ __forceinline__ void ldsm_x2(uint32_t& r0, uint32_t& r1, uint32_t a) {
    asm volatile("ldmatrix.sync.aligned.m8n8.x2.shared.b16 {%0,%1}, [%2];"
                 : "=r"(r0), "=r"(r1) : "r"(a));
}

__device__ __forceinline__ void ldsm_x4t(uint32_t* r, uint32_t a) {
    asm volatile("ldmatrix.sync.aligned.m8n8.x4.trans.shared.b16 {%0,%1,%2,%3}, [%4];"
                 : "=r"(r[0]), "=r"(r[1]), "=r"(r[2]), "=r"(r[3]) : "r"(a));
}

// fp16 MMA, fp32 accumulate
__device__ __forceinline__ void mma16816h(float* c, const uint32_t* A, const uint32_t* Bv) {
    asm volatile(
        "mma.sync.aligned.m16n8k16.row.col.f32.f16.f16.f32 "
        "{%0,%1,%2,%3}, {%4,%5,%6,%7}, {%8,%9}, {%0,%1,%2,%3};"
        : "+f"(c[0]), "+f"(c[1]), "+f"(c[2]), "+f"(c[3])
        : "r"(A[0]), "r"(A[1]), "r"(A[2]), "r"(A[3]), "r"(Bv[0]), "r"(Bv[1]));
}

__device__ __forceinline__ void cp16(uint32_t dst, const void* src) {
    asm volatile("cp.async.cg.shared.global [%0], [%1], 16;" :: "r"(dst), "l"(src));
}
#define CP_COMMIT() asm volatile("cp.async.commit_group;" ::: "memory")
#define CP_WAIT0()  asm volatile("cp.async.wait_group 0;" ::: "memory")

// pack two fp32 -> f16x2 {lo=p0, hi=p1}
__device__ __forceinline__ uint32_t pack_f16(float p0, float p1) {
    uint32_t r;
    asm("cvt.rn.f16x2.f32 %0, %1, %2;" : "=r"(r) : "f"(p1), "f"(p0));
    return r;
}

// split pair -> f16x2 hi + f16x2 residual
__device__ __forceinline__ void mk2h(float p0, float p1, uint32_t& hi, uint32_t& lo) {
    uint32_t h = pack_f16(p0, p1);
    __half2 hh = *reinterpret_cast<__half2*>(&h);
    float r0 = p0 - __low2float(hh);
    float r1 = p1 - __high2float(hh);
    hi = h;
    lo = pack_f16(r0, r1);
}

__device__ __forceinline__ void split2h(float x, unsigned short& hh, unsigned short& ll) {
    __half hb = __float2half_rn(x);
    hh = reinterpret_cast<unsigned short&>(hb);
    float r = x - __half2float(hb);
    __half lb = __float2half_rn(r);
    ll = reinterpret_cast<unsigned short&>(lb);
}

// ---------------------------------------------------------------------------
// Prep kernels (fp16 splits)
// ---------------------------------------------------------------------------
__global__ void __launch_bounds__(256) pack_split_kernel(
    const float* __restrict__ src, unsigned short* __restrict__ hi,
    unsigned short* __restrict__ lo)
{
    int i = blockIdx.x * 256 + threadIdx.x;
    float4 v = ((const float4*)src)[i];
    unsigned short h[4], l[4];
    split2h(v.x, h[0], l[0]); split2h(v.y, h[1], l[1]);
    split2h(v.z, h[2], l[2]); split2h(v.w, h[3], l[3]);
    ((uint2*)hi)[i] = make_uint2((uint32_t)h[0] | ((uint32_t)h[1] << 16),
                                 (uint32_t)h[2] | ((uint32_t)h[3] << 16));
    ((uint2*)lo)[i] = make_uint2((uint32_t)l[0] | ((uint32_t)l[1] << 16),
                                 (uint32_t)l[2] | ((uint32_t)l[3] << 16));
}

// w [K,N] fp32 -> wT hi fp16 [N,K] (hi only — 2-term GEMM drops B lo)
__global__ void __launch_bounds__(256) transpose_pack_kernel(
    const float* __restrict__ w, unsigned short* __restrict__ th, int K, int N)
{
    __shared__ float tile[32][33];
    const int k0 = blockIdx.y * 32, n0 = blockIdx.x * 32;
    const int tx = threadIdx.x, ty = threadIdx.y;   // 32 x 8
    #pragma unroll
    for (int i = 0; i < 32; i += 8)
        tile[ty + i][tx] = w[(size_t)(k0 + ty + i) * N + n0 + tx];
    __syncthreads();
    #pragma unroll
    for (int i = 0; i < 32; i += 8) {
        int n = n0 + ty + i;
        int k = k0 + tx;
        __half hv = __float2half_rn(tile[tx][ty + i]);
        th[(size_t)n * K + k] = reinterpret_cast<unsigned short&>(hv);
    }
}

// ---------------------------------------------------------------------------
// 2-term fp16 mma.sync GEMM: out = (Ah+Al) @ Bh^T + bias.
// BM=BN=128, BK=32, 8 warps (2x4), warp tile 64x32, 2-stage cp.async.
// Stage: Ah 8K | Al 8K | Bh 8K = 24KB.
// ---------------------------------------------------------------------------
#define GEMM_SMEM (2*24576)

__global__ void __launch_bounds__(256) gemm_mma_kernel(
    const unsigned short* __restrict__ ah, const unsigned short* __restrict__ al,
    const unsigned short* __restrict__ bh,
    const float* __restrict__ bias, float* __restrict__ outf,
    unsigned short* __restrict__ outh, unsigned short* __restrict__ outl,
    int M, int N, int K)
{
    extern __shared__ char smc[];
    const uint32_t sbase = smem_u32(smc);
    const int tid  = threadIdx.x;
    const int wid  = tid >> 5, lane = tid & 31;
    const int wm   = wid >> 2, wn = wid & 3;
    const int mBase = blockIdx.y * 128;
    const int nBase = blockIdx.x * 128;
    const int nk = K >> 5;

    const int r0c = tid >> 2;
    const int c0c = tid & 3;
    auto sw = [](int r, int c) { return r * 64 + ((c ^ ((r >> 1) & 3)) << 4); };

    auto issue = [&](int ks, int stage) {
        const int kb = ks << 5;
        const unsigned short* gs[3] = { ah, al, bh };
        #pragma unroll
        for (int part = 0; part < 3; part++) {
            const unsigned short* g = gs[part] +
                (size_t)((part < 2) ? mBase : nBase) * K + kb;
            uint32_t pb = sbase + stage * 24576 + part * 8192;
            cp16(pb + sw(r0c,      c0c), g + (size_t)r0c        * K + c0c * 8);
            cp16(pb + sw(r0c + 64, c0c), g + (size_t)(r0c + 64) * K + c0c * 8);
        }
        CP_COMMIT();
    };

    float acc[4][4][4];
    #pragma unroll
    for (int i = 0; i < 4; i++)
        #pragma unroll
        for (int j = 0; j < 4; j++)
            #pragma unroll
            for (int r = 0; r < 4; r++) acc[i][j][r] = 0.f;

    const int la_row = lane & 15;
    const int la_kh  = lane >> 4;
    const int lb_row = lane & 7;
    const int lb_kh  = (lane >> 3) & 1;

    issue(0, 0);

    for (int ks = 0; ks < nk; ks++) {
        const int cur = ks & 1;
        CP_WAIT0();
        __syncthreads();
        if (ks + 1 < nk) issue(ks + 1, cur ^ 1);

        const uint32_t sAh = sbase + cur * 24576;
        const uint32_t sAl = sAh + 8192;
        const uint32_t sBh = sAh + 16384;

        #pragma unroll
        for (int kk = 0; kk < 2; kk++) {
            const int ch_a = kk * 2 + la_kh;
            const int ch_b = kk * 2 + lb_kh;

            uint32_t Ahf[4][4], Bhf[4][2];
            #pragma unroll
            for (int i = 0; i < 4; i++) {
                int row = wm * 64 + i * 16 + la_row;
                ldsm_x4(Ahf[i][0], Ahf[i][1], Ahf[i][2], Ahf[i][3], sAh + sw(row, ch_a));
            }
            #pragma unroll
            for (int j = 0; j < 4; j++) {
                int row = wn * 32 + j * 8 + lb_row;
                ldsm_x2(Bhf[j][0], Bhf[j][1], sBh + sw(row, ch_b));
            }
            #pragma unroll
            for (int i = 0; i < 4; i++)
                #pragma unroll
                for (int j = 0; j < 4; j++) mma16816h(acc[i][j], Ahf[i], Bhf[j]);

            // Al x Bh (reuse Bh fragments)
            uint32_t Alf[4][4];
            #pragma unroll
            for (int i = 0; i < 4; i++) {
                int row = wm * 64 + i * 16 + la_row;
                ldsm_x4(Alf[i][0], Alf[i][1], Alf[i][2], Alf[i][3], sAl + sw(row, ch_a));
            }
            #pragma unroll
            for (int i = 0; i < 4; i++)
                #pragma unroll
                for (int j = 0; j < 4; j++) mma16816h(acc[i][j], Alf[i], Bhf[j]);
        }
    }

    // Epilogue
    const int g = lane >> 2, q = lane & 3;
    #pragma unroll
    for (int i = 0; i < 4; i++) {
        const int row0 = mBase + wm * 64 + i * 16 + g;
        #pragma unroll
        for (int j = 0; j < 4; j++) {
            const int col = nBase + wn * 32 + j * 8 + q * 2;
            float2 bb = *(const float2*)(bias + col);
            float v0x = acc[i][j][0] + bb.x, v0y = acc[i][j][1] + bb.y;
            float v1x = acc[i][j][2] + bb.x, v1y = acc[i][j][3] + bb.y;
            if (outh) {
                uint32_t h0, l0, h1, l1;
                mk2h(v0x, v0y, h0, l0);
                mk2h(v1x, v1y, h1, l1);
                *(uint32_t*)(outh + (size_t)row0 * N + col)       = h0;
                *(uint32_t*)(outl + (size_t)row0 * N + col)       = l0;
                *(uint32_t*)(outh + (size_t)(row0 + 8) * N + col) = h1;
                *(uint32_t*)(outl + (size_t)(row0 + 8) * N + col) = l1;
            } else {
                *(float2*)(outf + (size_t)row0 * N + col)       = make_float2(v0x, v0y);
                *(float2*)(outf + (size_t)(row0 + 8) * N + col) = make_float2(v1x, v1y);
            }
        }
    }
}

// ---------------------------------------------------------------------------
// Tensor-core flash attention (causal, fp16).  (unchanged from R9 win,
// except epilogue emits split-fp16 for the fp16 proj GEMM)
// ---------------------------------------------------------------------------
#define ATTN_SMEM (32768 + 2*24576)

__global__ void __launch_bounds__(256, 2) attn_mma_kernel(
    const unsigned short* __restrict__ qkvh,
    const unsigned short* __restrict__ qkvl,
    unsigned short* __restrict__ atth,
    unsigned short* __restrict__ attl)
{
    extern __shared__ char smc[];
    const uint32_t sb = smem_u32(smc);
    const int tid = threadIdx.x, lane = tid & 31, w = tid >> 5;
    const int bh = blockIdx.y, b = bh >> 4, hd = bh & 15;
    const int qb = (int)gridDim.x - 1 - (int)blockIdx.x;   // big blocks first
    const int q0 = qb * 128;
    const int nkt = 2 * qb + 2;

    const size_t base = (size_t)b * T_ * 3072 + hd * 64;
    const unsigned short* qh = qkvh + base;
    const unsigned short* qlp = qkvl + base;
    const unsigned short* kh = qh + 1024;
    const unsigned short* vh = qh + 2048;
    const unsigned short* vl = qlp + 2048;

    const uint32_t sQh = sb, sQl = sb + 16384;
    auto stage0 = [&](int s) { return sb + 32768 + s * 24576; };
    auto off = [](int r, int c) { return r * 128 + ((c ^ (r & 7)) << 4); };

    auto issue_kv = [&](int kt, int s) {
        uint32_t sn = stage0(s);
        const size_t kb = (size_t)kt * 64;
        #pragma unroll
        for (int i = 0; i < 2; i++) {
            int idx = i * 256 + tid;
            int r = idx >> 3, c = idx & 7;
            const size_t g = (kb + r) * 3072 + c * 8;
            cp16(sn +         off(r, c), kh + g);
            cp16(sn + 8192 +  off(r, c), vh + g);
            cp16(sn + 16384 + off(r, c), vl + g);
        }
        CP_COMMIT();
    };

    // prologue: Q (hi+lo) + K/V tile 0, one commit group
    #pragma unroll
    for (int i = 0; i < 4; i++) {
        int idx = i * 256 + tid;
        int r = idx >> 3, c = idx & 7;
        const size_t g = (size_t)(q0 + r) * 3072 + c * 8;
        cp16(sQh + off(r, c), qh + g);
        cp16(sQl + off(r, c), qlp + g);
    }
    issue_kv(0, 0);

    float O[8][4], s[8][4];
    #pragma unroll
    for (int j = 0; j < 8; j++) { O[j][0] = O[j][1] = O[j][2] = O[j][3] = 0.f; }
    float m_lo = -1e30f, m_hi = -1e30f, l_lo = 0.f, l_hi = 0.f;

    const int la_row = lane & 15, la_kh = lane >> 4;
    const int kb_row = ((lane >> 4) << 3) + (lane & 7);
    const int kb_ch  = (lane >> 3) & 1;
    const int vb_row = (((lane >> 3) & 1) << 3) + (lane & 7);
    const int vb_ch  = lane >> 4;
    const int rowq_lo = q0 + w * 16 + (lane >> 2);
    const float SC = 0.125f * 1.4426950408889634f;   // scale * log2(e)

    for (int kt = 0; kt < nkt; kt++) {
        const int cur = kt & 1;
        CP_WAIT0();
        __syncthreads();
        if (kt + 1 < nkt) issue_kv(kt + 1, cur ^ 1);

        const int k0 = kt * 64;
        const bool active = (k0 <= q0 + w * 16 + 15);
        if (active) {
            const uint32_t cK  = stage0(cur);
            const uint32_t cV  = cK + 8192;
            const uint32_t cVl = cK + 16384;

            // ---- S = Q K^T (fp16 2-term: QhKh + QlKh) ----
            #pragma unroll
            for (int j = 0; j < 8; j++) { s[j][0] = s[j][1] = s[j][2] = s[j][3] = 0.f; }
            #pragma unroll
            for (int kk = 0; kk < 4; kk++) {
                uint32_t aqh[4], aql[4];
                ldsm_x4(aqh[0], aqh[1], aqh[2], aqh[3],
                        sQh + off(w * 16 + la_row, 2 * kk + la_kh));
                ldsm_x4(aql[0], aql[1], aql[2], aql[3],
                        sQl + off(w * 16 + la_row, 2 * kk + la_kh));
                #pragma unroll
                for (int j2 = 0; j2 < 4; j2++) {
                    uint32_t bk[4];
                    ldsm_x4(bk[0], bk[1], bk[2], bk[3],
                            cK + off(16 * j2 + kb_row, 2 * kk + kb_ch));
                    mma16816h(s[2 * j2],     aqh, bk);
                    mma16816h(s[2 * j2 + 1], aqh, bk + 2);
                    mma16816h(s[2 * j2],     aql, bk);
                    mma16816h(s[2 * j2 + 1], aql, bk + 2);
                }
            }

            // ---- online softmax (exp2 domain) ----
            const bool masked = (k0 + 63 > q0 + w * 16);
            float rm_lo = -1e30f, rm_hi = -1e30f;
            #pragma unroll
            for (int j = 0; j < 8; j++) {
                int colb = k0 + 8 * j + 2 * (lane & 3);
                #pragma unroll
                for (int e = 0; e < 2; e++) {
                    float v = s[j][e] * SC;
                    if (masked && (colb + e) > rowq_lo) v = -1e30f;
                    s[j][e] = v; rm_lo = fmaxf(rm_lo, v);
                    float v2 = s[j][2 + e] * SC;
                    if (masked && (colb + e) > rowq_lo + 8) v2 = -1e30f;
                    s[j][2 + e] = v2; rm_hi = fmaxf(rm_hi, v2);
                }
            }
            rm_lo = fmaxf(rm_lo, __shfl_xor_sync(0xffffffffu, rm_lo, 1));
            rm_lo = fmaxf(rm_lo, __shfl_xor_sync(0xffffffffu, rm_lo, 2));
            rm_hi = fmaxf(rm_hi, __shfl_xor_sync(0xffffffffu, rm_hi, 1));
            rm_hi = fmaxf(rm_hi, __shfl_xor_sync(0xffffffffu, rm_hi, 2));
            float mn_lo = fmaxf(m_lo, rm_lo), mn_hi = fmaxf(m_hi, rm_hi);
            float corr_lo = exp2f(m_lo - mn_lo), corr_hi = exp2f(m_hi - mn_hi);
            m_lo = mn_lo; m_hi = mn_hi;
            float ps_lo = 0.f, ps_hi = 0.f;
            #pragma unroll
            for (int j = 0; j < 8; j++) {
                s[j][0] = exp2f(s[j][0] - mn_lo);
                s[j][1] = exp2f(s[j][1] - mn_lo);
                s[j][2] = exp2f(s[j][2] - mn_hi);
                s[j][3] = exp2f(s[j][3] - mn_hi);
                ps_lo += s[j][0] + s[j][1];
                ps_hi += s[j][2] + s[j][3];
            }
            ps_lo += __shfl_xor_sync(0xffffffffu, ps_lo, 1);
            ps_lo += __shfl_xor_sync(0xffffffffu, ps_lo, 2);
            ps_hi += __shfl_xor_sync(0xffffffffu, ps_hi, 1);
            ps_hi += __shfl_xor_sync(0xffffffffu, ps_hi, 2);
            l_lo = l_lo * corr_lo + ps_lo;
            l_hi = l_hi * corr_hi + ps_hi;
            #pragma unroll
            for (int j = 0; j < 8; j++) {
                O[j][0] *= corr_lo; O[j][1] *= corr_lo;
                O[j][2] *= corr_hi; O[j][3] *= corr_hi;
            }

            // ---- O += P V (P fp16 single; V fp16 2-term) ----
            #pragma unroll
            for (int t = 0; t < 4; t++) {
                uint32_t ph[4];
                ph[0] = pack_f16(s[2 * t][0],     s[2 * t][1]);
                ph[1] = pack_f16(s[2 * t][2],     s[2 * t][3]);
                ph[2] = pack_f16(s[2 * t + 1][0], s[2 * t + 1][1]);
                ph[3] = pack_f16(s[2 * t + 1][2], s[2 * t + 1][3]);
                #pragma unroll
                for (int j2 = 0; j2 < 4; j2++) {
                    uint32_t bv[4];
                    ldsm_x4t(bv, cV + off(16 * t + vb_row, 2 * j2 + vb_ch));
                    mma16816h(O[2 * j2],     ph, bv);
                    mma16816h(O[2 * j2 + 1], ph, bv + 2);
                    ldsm_x4t(bv, cVl + off(16 * t + vb_row, 2 * j2 + vb_ch));
                    mma16816h(O[2 * j2],     ph, bv);
                    mma16816h(O[2 * j2 + 1], ph, bv + 2);
                }
            }
        }
    }

    // ---- epilogue: normalize, split-fp16, write ----
    const float inv_lo = 1.f / l_lo, inv_hi = 1.f / l_hi;
    const size_t row_lo = (size_t)(b * T_) + q0 + w * 16 + (lane >> 2);
    const int colb = hd * 64 + 2 * (lane & 3);
    #pragma unroll
    for (int j = 0; j < 8; j++) {
        const int col = colb + 8 * j;
        uint32_t h0, l0, h1, l1;
        mk2h(O[j][0] * inv_lo, O[j][1] * inv_lo, h0, l0);
        mk2h(O[j][2] * inv_hi, O[j][3] * inv_hi, h1, l1);
        *(uint32_t*)(atth + row_lo * C_ + col)       = h0;
        *(uint32_t*)(attl + row_lo * C_ + col)       = l0;
        *(uint32_t*)(atth + (row_lo + 8) * C_ + col) = h1;
        *(uint32_t*)(attl + (row_lo + 8) * C_ + col) = l1;
    }
}

// ---------------------------------------------------------------------------
extern "C" void kernel_launch(void* const* d_in, const int* in_sizes, int n_in,
                              void* d_out, int out_size)
{
    const float* x      = (const float*)d_in[0];
    const float* w_qkv  = (const float*)d_in[1];
    const float* b_qkv  = (const float*)d_in[2];
    const float* w_proj = (const float*)d_in[3];
    const float* b_proj = (const float*)d_in[4];
    float* out = (float*)d_out;

    unsigned short *qvh, *qvl, *xh, *xl, *wqh, *wph, *ath, *atl;
    cudaGetSymbolAddress((void**)&qvh, g_qkvh);
    cudaGetSymbolAddress((void**)&qvl, g_qkvl);
    cudaGetSymbolAddress((void**)&xh, g_xh);
    cudaGetSymbolAddress((void**)&xl, g_xl);
    cudaGetSymbolAddress((void**)&wqh, g_wqkvh);
    cudaGetSymbolAddress((void**)&wph, g_wprojh);
    cudaGetSymbolAddress((void**)&ath, g_atth);
    cudaGetSymbolAddress((void**)&atl, g_attl);

    cudaFuncSetAttribute(gemm_mma_kernel,
                         cudaFuncAttributeMaxDynamicSharedMemorySize, GEMM_SMEM);
    cudaFuncSetAttribute(attn_mma_kernel,
                         cudaFuncAttributeMaxDynamicSharedMemorySize, ATTN_SMEM);

    // 0) pack inputs to fp16 splits (weights: hi only)
    pack_split_kernel<<<M_*C_/1024, 256>>>(x, xh, xl);
    transpose_pack_kernel<<<dim3(3*C_/32, C_/32), dim3(32, 8)>>>(w_qkv, wqh, C_, 3*C_);
    transpose_pack_kernel<<<dim3(C_/32, C_/32), dim3(32, 8)>>>(w_proj, wph, C_, C_);

    // 1) qkv = x @ w_qkv + b_qkv  -> split-fp16 qkv
    gemm_mma_kernel<<<dim3(3*C_/128, M_/128), 256, GEMM_SMEM>>>(
        xh, xl, wqh, b_qkv, nullptr, qvh, qvl, M_, 3*C_, C_);

    // 2) tensor-core causal flash attention (fp16) -> split-fp16 att
    attn_mma_kernel<<<dim3(T_/128, B_*H_), 256, ATTN_SMEM>>>(qvh, qvl, ath, atl);

    // 3) out = att @ w_proj + b_proj  -> fp32
    gemm_mma_kernel<<<dim3(C_/128, M_/128), 256, GEMM_SMEM>>>(
        ath, atl, wph, b_proj, out, nullptr, nullptr, M_, C_, C_);
}